// round 12
// baseline (speedup 1.0000x reference)
#include <cuda_runtime.h>
#include <cuda_bf16.h>
#include <cstdint>

// ---------------------------------------------------------------------------
// InputStem R12: conv1 FFMA2 (NHWC) + m64 z-ring HMMA conv2 + stride-2 z-ring
// HMMA conv3 + HMMA bf16x3 patch GEMM with fused BN2+decomp A-fill.
// ---------------------------------------------------------------------------

#define VOL_FULL (128*128*128)
#define VOL_HALF (64*64*64)
#define N_PATCH  343
#define N_T      160
#define PDIM     131072

typedef unsigned long long u64;

__device__ float  g_buf1[(size_t)2*VOL_FULL*16];   // conv1 raw, NHWC fp32
__device__ float  g_buf2[(size_t)2*VOL_FULL*16];   // conv2 raw, NHWC fp32
__device__ float  g_buf3[2*32*VOL_HALF];           // conv3 raw, NCHW fp32
__device__ double g_redp[3][64][64];
__device__ float  g_sbt[3][64];
__device__ float  g_gemm[2*N_PATCH*N_T];

__device__ __nv_bfloat16 g_whi[(size_t)N_T*PDIM];
__device__ __nv_bfloat16 g_wlo[(size_t)N_T*PDIM];
__device__ __nv_bfloat16 g_w2h[6912];
__device__ __nv_bfloat16 g_w2l[6912];
__device__ __nv_bfloat16 g_w3h[13824];
__device__ __nv_bfloat16 g_w3l[13824];

__device__ __forceinline__ u64 pk2(float x, float y) {
    u64 r; asm("mov.b64 %0,{%1,%2};" : "=l"(r) : "f"(x), "f"(y)); return r;
}
__device__ __forceinline__ float2 upk(u64 v) {
    float2 r; asm("mov.b64 {%0,%1},%2;" : "=f"(r.x), "=f"(r.y) : "l"(v)); return r;
}
__device__ __forceinline__ void fma2(u64& d, u64 a, u64 b) {
    asm("fma.rn.f32x2 %0,%1,%2,%0;" : "+l"(d) : "l"(a), "l"(b));
}
__device__ __forceinline__ uint32_t smem_u32(const void* p) {
    uint32_t a;
    asm("{ .reg .u64 t; cvta.to.shared.u64 t, %1; cvt.u32.u64 %0, t; }" : "=r"(a) : "l"(p));
    return a;
}
__device__ __forceinline__ void ldsm4(uint32_t* r, uint32_t addr) {
    asm volatile("ldmatrix.sync.aligned.m8n8.x4.shared.b16 {%0,%1,%2,%3}, [%4];"
        : "=r"(r[0]), "=r"(r[1]), "=r"(r[2]), "=r"(r[3]) : "r"(addr));
}
__device__ __forceinline__ void mma_bf16(float* d, const uint32_t* a,
                                         uint32_t b0, uint32_t b1) {
    asm volatile("mma.sync.aligned.m16n8k16.row.col.f32.bf16.bf16.f32 "
        "{%0,%1,%2,%3}, {%4,%5,%6,%7}, {%8,%9}, {%0,%1,%2,%3};"
        : "+f"(d[0]), "+f"(d[1]), "+f"(d[2]), "+f"(d[3])
        : "r"(a[0]), "r"(a[1]), "r"(a[2]), "r"(a[3]), "r"(b0), "r"(b1));
}

// ---------------------------------------------------------------------------
__global__ void k_zero() {
    int i = blockIdx.x * blockDim.x + threadIdx.x;
    if (i < 2*N_PATCH*N_T) g_gemm[i] = 0.f;
    if (i < 3*64*64) ((double*)g_redp)[i] = 0.0;
}

// ---------------------------------------------------------------------------
// conv1: 1->16, FFMA2, TWO y-rows; NHWC fp32 out via smem staging; stats 0.
__global__ void __launch_bounds__(128) k_conv1(const float* __restrict__ in,
                                               const float* __restrict__ w)
{
    __shared__ __align__(16) float sm_in[13*128];
    __shared__ float sm_w[27*16];
    __shared__ __align__(16) float sm_out[2*16*132];
    const int y0 = 2*blockIdx.x, z = blockIdx.y, b = blockIdx.z;
    const int t = threadIdx.x, l = t & 31, g = t >> 5;

    for (int i = t; i < 27*16; i += 128) {
        int co = i & 15, k = i >> 4;
        sm_w[i] = w[co*27 + k];
    }
    {
        const float* inc = in + (size_t)b * VOL_FULL;
#pragma unroll
        for (int j = 0; j < 13; j++) {
            int i = t + 128*j;
            float v = 0.f;
            if (i < 1584) {
                int r = i / 132, idx = i - 132*r;
                int gz = z - 1 + (r >> 2), gy = y0 - 1 + (r & 3), gx = idx - 1;
                if ((unsigned)gz < 128u && (unsigned)gy < 128u && (unsigned)gx < 128u)
                    v = inc[(gz*128 + gy)*128 + gx];
            }
            if (i < 13*128) sm_in[i] = v;
        }
    }
    __syncthreads();

    u64 acc[2][2][4];
#pragma unroll
    for (int yr = 0; yr < 2; yr++)
#pragma unroll
        for (int j2 = 0; j2 < 2; j2++)
#pragma unroll
            for (int xx = 0; xx < 4; xx++) acc[yr][j2][xx] = 0ULL;

#pragma unroll
    for (int r = 0; r < 12; r++) {
        float4 A = *(const float4*)(sm_in + r*132 + 4*l);
        float4 B = *(const float4*)(sm_in + r*132 + 4*l + 4);
        float a[7] = {A.x, A.y, A.z, A.w, B.x, B.y, B.z};
        u64 pv[7];
#pragma unroll
        for (int j = 0; j < 7; j++) pv[j] = pk2(a[j], a[j]);
        const int dz = r >> 2, m = r & 3;
#pragma unroll
        for (int yr = 0; yr < 2; yr++) {
            const int dyy = m - yr;
            if (dyy < 0 || dyy > 2) continue;
            const int kb = dz*9 + dyy*3;
#pragma unroll
            for (int dx = 0; dx < 3; dx++) {
                u64 w0 = *(const u64*)(sm_w + (kb+dx)*16 + g*4);
                u64 w1 = *(const u64*)(sm_w + (kb+dx)*16 + g*4 + 2);
#pragma unroll
                for (int xx = 0; xx < 4; xx++) {
                    fma2(acc[yr][0][xx], pv[dx+xx], w0);
                    fma2(acc[yr][1][xx], pv[dx+xx], w1);
                }
            }
        }
    }

    float2 v[2][2][4];
#pragma unroll
    for (int yr = 0; yr < 2; yr++)
#pragma unroll
        for (int j2 = 0; j2 < 2; j2++)
#pragma unroll
            for (int xx = 0; xx < 4; xx++) v[yr][j2][xx] = upk(acc[yr][j2][xx]);

#pragma unroll
    for (int yr = 0; yr < 2; yr++)
#pragma unroll
        for (int j2 = 0; j2 < 2; j2++) {
            int co = g*4 + 2*j2;
#pragma unroll
            for (int xx = 0; xx < 4; xx++) {
                sm_out[(yr*16 + co)*132 + 4*l + xx]   = v[yr][j2][xx].x;
                sm_out[(yr*16 + co+1)*132 + 4*l + xx] = v[yr][j2][xx].y;
            }
        }
    __syncthreads();

#pragma unroll
    for (int p = 0; p < 2; p++) {
        int vox = t + 128*p;
        int yr = vox >> 7, x = vox & 127;
        float o[16];
#pragma unroll
        for (int c = 0; c < 16; c++) o[c] = sm_out[(yr*16 + c)*132 + x];
        float* dst = g_buf1 + ((size_t)b*VOL_FULL + ((size_t)z*128 + y0 + yr)*128 + x)*16;
        *(float4*)(dst)      = make_float4(o[0], o[1], o[2], o[3]);
        *(float4*)(dst + 4)  = make_float4(o[4], o[5], o[6], o[7]);
        *(float4*)(dst + 8)  = make_float4(o[8], o[9], o[10], o[11]);
        *(float4*)(dst + 12) = make_float4(o[12], o[13], o[14], o[15]);
    }

#pragma unroll
    for (int c = 0; c < 4; c++) {
        float s = 0.f, q = 0.f;
#pragma unroll
        for (int yr = 0; yr < 2; yr++)
#pragma unroll
            for (int xx = 0; xx < 4; xx++) {
                float val = (c & 1) ? v[yr][c>>1][xx].y : v[yr][c>>1][xx].x;
                s += val; q = fmaf(val, val, q);
            }
#pragma unroll
        for (int o = 16; o; o >>= 1) {
            s += __shfl_down_sync(0xffffffffu, s, o);
            q += __shfl_down_sync(0xffffffffu, q, o);
        }
        if (l == 0) {
            atomicAdd(&g_redp[0][z & 63][g*4 + c],      (double)s);
            atomicAdd(&g_redp[0][z & 63][32 + g*4 + c], (double)q);
        }
    }
}

// ---------------------------------------------------------------------------
__global__ void k_decompW2(const float* __restrict__ w) {
    for (int i = threadIdx.x; i < 6912; i += 256) {
        int ci = i & 15, co = (i >> 4) & 15, tap = i >> 8;
        float v = w[(co*16 + ci)*27 + tap];
        __nv_bfloat16 h = __float2bfloat16(v);
        g_w2h[i] = h;
        g_w2l[i] = __float2bfloat16(v - __bfloat162float(h));
    }
}
__global__ void k_decompW3(const float* __restrict__ w) {
    for (int i = threadIdx.x; i < 13824; i += 256) {
        int ci = i & 15, co = (i >> 4) & 31, tap = i >> 9;
        float v = w[(co*16 + ci)*27 + tap];
        __nv_bfloat16 h = __float2bfloat16(v);
        g_w3h[i] = h;
        g_w3l[i] = __float2bfloat16(v - __bfloat162float(h));
    }
}

// ---------------------------------------------------------------------------
// conv2 ring2 m64: 4 y-rows, 16 z, 256 thr / 8 warps: warp = (yr=wid>>1,
// xt=wid&1), 4 m16 tiles (m64) share each B fragment.
#define R2_SLOT   24960
#define R2_ALO    99840
#define R2_BHI    199680
#define R2_BLO    213504
#define R2_SB     227328
#define R2_SMEM   227584

__global__ void __launch_bounds__(256, 1) k_conv2_ring2()
{
    extern __shared__ __align__(16) char smem[];
    const uint32_t sb = smem_u32(smem);
    float* smSB = (float*)(smem + R2_SB);
    const int yq = blockIdx.x, zs = blockIdx.y, b = blockIdx.z;
    const int y0 = 4*yq, z0 = 16*zs;
    const int tid = threadIdx.x, wid = tid >> 5, lane = tid & 31;

    if (tid < 64) smSB[tid] = g_sbt[0][tid];

    for (int i = tid; i < 864; i += 256) {
        int row = i >> 1, hf = i & 1;
        uint4 vh = *(const uint4*)(g_w2h + row*16 + hf*8);
        uint4 vl = *(const uint4*)(g_w2l + row*16 + hf*8);
        uint32_t off = (uint32_t)row*32 + (((uint32_t)hf ^ ((uint32_t)(row>>2)&1)) << 4);
        *(uint4*)(smem + R2_BHI + off) = vh;
        *(uint4*)(smem + R2_BLO + off) = vl;
    }
    __syncthreads();

    auto fillplane = [&](int p) {
        int slot = (p & 3);
        char* ah = smem + slot*R2_SLOT;
        char* al = smem + R2_ALO + slot*R2_SLOT;
        for (int i = tid; i < 780; i += 256) {
            int dyr = i / 130, xs = i - dyr*130;
            int gx = xs - 1, gy = y0 - 1 + dyr;
            __align__(16) __nv_bfloat16 h[16], lo[16];
            if ((unsigned)p < 128u && (unsigned)gy < 128u && (unsigned)gx < 128u) {
                const float4* src = (const float4*)(g_buf1
                    + ((size_t)b*VOL_FULL + ((size_t)p*128 + gy)*128 + gx)*16);
                float4 q0 = src[0], q1 = src[1], q2 = src[2], q3 = src[3];
                float f[16] = {q0.x,q0.y,q0.z,q0.w, q1.x,q1.y,q1.z,q1.w,
                               q2.x,q2.y,q2.z,q2.w, q3.x,q3.y,q3.z,q3.w};
#pragma unroll
                for (int c = 0; c < 16; c++) {
                    float vv = fmaxf(fmaf(f[c], smSB[c], smSB[32 + c]), 0.f);
                    h[c] = __float2bfloat16(vv);
                    lo[c] = __float2bfloat16(vv - __bfloat162float(h[c]));
                }
            } else {
#pragma unroll
                for (int c = 0; c < 16; c++) { h[c] = __float2bfloat16(0.f); lo[c] = h[c]; }
            }
            uint32_t pb = (uint32_t)((i >> 2) & 1);
            uint32_t o0 = (uint32_t)i*32 + (pb << 4);
            uint32_t o1 = (uint32_t)i*32 + ((1u ^ pb) << 4);
            *(uint4*)(ah + o0) = *(uint4*)h;
            *(uint4*)(ah + o1) = *(uint4*)(h + 8);
            *(uint4*)(al + o0) = *(uint4*)lo;
            *(uint4*)(al + o1) = *(uint4*)(lo + 8);
        }
    };

    fillplane(z0 - 1);
    fillplane(z0);

    const int yr = wid >> 1, xt = wid & 1;
    const int mrow = lane & 15;
    const uint32_t ahalf = (uint32_t)(lane >> 4);
    const int browl = ((lane >> 4) << 3) + (lane & 7);
    const uint32_t bhalf = (uint32_t)((lane >> 3) & 1);

    float sacc[4] = {0.f,0.f,0.f,0.f}, qacc[4] = {0.f,0.f,0.f,0.f};

    for (int z = z0; z < z0 + 16; z++) {
        fillplane(z + 1);
        __syncthreads();

        uint32_t sb_a[3];
#pragma unroll
        for (int dz = 0; dz < 3; dz++)
            sb_a[dz] = (uint32_t)(((z - 1 + dz) & 3) * R2_SLOT);

        float d[4][2][4];
#pragma unroll
        for (int mt = 0; mt < 4; mt++)
#pragma unroll
            for (int nt = 0; nt < 2; nt++)
#pragma unroll
                for (int i = 0; i < 4; i++) d[mt][nt][i] = 0.f;

#pragma unroll
        for (int tap = 0; tap < 27; tap++) {
            const int zy = tap / 3, dx = tap % 3;
            const int dz = zy / 3, dy = zy % 3;

            int br = tap*16 + browl;
            uint32_t boff = (uint32_t)br*32
                          + ((bhalf ^ ((uint32_t)(br >> 2) & 1)) << 4);
            uint32_t bh4[4], bl4[4];
            ldsm4(bh4, sb + R2_BHI + boff);
            ldsm4(bl4, sb + R2_BLO + boff);

#pragma unroll
            for (int mt = 0; mt < 4; mt++) {
                int r = (yr + dy)*130 + 64*xt + 16*mt + dx + mrow;
                uint32_t aoff = sb_a[dz] + (uint32_t)r*32
                              + ((ahalf ^ ((uint32_t)(r >> 2) & 1)) << 4);
                uint32_t ah4[4], al4[4];
                ldsm4(ah4, sb + aoff);
                ldsm4(al4, sb + R2_ALO + aoff);

                mma_bf16(d[mt][0], ah4, bh4[0], bh4[1]);
                mma_bf16(d[mt][1], ah4, bh4[2], bh4[3]);
                mma_bf16(d[mt][0], ah4, bl4[0], bl4[1]);
                mma_bf16(d[mt][1], ah4, bl4[2], bl4[3]);
                mma_bf16(d[mt][0], al4, bh4[0], bh4[1]);
                mma_bf16(d[mt][1], al4, bh4[2], bh4[3]);
            }
        }

        // NHWC stores + running stats
#pragma unroll
        for (int mt = 0; mt < 4; mt++) {
            int x = 64*xt + 16*mt + (lane >> 2);
            size_t vbase = ((size_t)b*VOL_FULL + ((size_t)z*128 + y0 + yr)*128 + x)*16;
#pragma unroll
            for (int nt = 0; nt < 2; nt++) {
                int c = 8*nt + 2*(lane & 3);
                *(float2*)(g_buf2 + vbase + c)       = make_float2(d[mt][nt][0], d[mt][nt][1]);
                *(float2*)(g_buf2 + vbase + 128 + c) = make_float2(d[mt][nt][2], d[mt][nt][3]);
                sacc[2*nt]   += d[mt][nt][0] + d[mt][nt][2];
                sacc[2*nt+1] += d[mt][nt][1] + d[mt][nt][3];
                qacc[2*nt]   += d[mt][nt][0]*d[mt][nt][0] + d[mt][nt][2]*d[mt][nt][2];
                qacc[2*nt+1] += d[mt][nt][1]*d[mt][nt][1] + d[mt][nt][3]*d[mt][nt][3];
            }
        }
    }

    __syncthreads();
    float* smS = (float*)smem;
    if (tid < 32) smS[tid] = 0.f;
    __syncthreads();
#pragma unroll
    for (int k = 0; k < 4; k++) {
        int c = 8*(k >> 1) + 2*(lane & 3) + (k & 1);
        atomicAdd(&smS[c], sacc[k]);
        atomicAdd(&smS[16 + c], qacc[k]);
    }
    __syncthreads();
    if (tid < 16) {
        int slot = (yq*8 + zs) & 63;
        atomicAdd(&g_redp[1][slot][tid],      (double)smS[tid]);
        atomicAdd(&g_redp[1][slot][32 + tid], (double)smS[16 + tid]);
    }
}

// ---------------------------------------------------------------------------
// conv3 ring (R11): stride-2 16->32 HMMA bf16x3.
#define C3_SLOT 20800
#define C3_ALO  83200
#define C3_BHI  166400
#define C3_BLO  194048
#define C3_SB   221696
#define C3_SMEM 221952

__global__ void __launch_bounds__(256, 1) k_conv3_ring()
{
    extern __shared__ __align__(16) char smem[];
    const uint32_t sb = smem_u32(smem);
    float* smSB = (float*)(smem + C3_SB);
    const int yq = blockIdx.x, zs = blockIdx.y, b = blockIdx.z;
    const int y0 = 2*yq, z0 = 16*zs;
    const int tid = threadIdx.x, wid = tid >> 5, lane = tid & 31;

    if (tid < 64) smSB[tid] = g_sbt[1][tid];

    for (int i = tid; i < 1728; i += 256) {
        int row = i >> 1, hf = i & 1;
        uint4 vh = *(const uint4*)(g_w3h + row*16 + hf*8);
        uint4 vl = *(const uint4*)(g_w3l + row*16 + hf*8);
        uint32_t off = (uint32_t)row*32 + (((uint32_t)hf ^ ((uint32_t)(row>>2)&1)) << 4);
        *(uint4*)(smem + C3_BHI + off) = vh;
        *(uint4*)(smem + C3_BLO + off) = vl;
    }
    __syncthreads();

    auto fillplane = [&](int p) {
        int slot = (p & 3);
        char* ah = smem + slot*C3_SLOT;
        char* al = smem + C3_ALO + slot*C3_SLOT;
        for (int i = tid; i < 650; i += 256) {
            int dyr = i / 130, xs = i - dyr*130;
            int gx = xs - 1, gy = 2*y0 - 1 + dyr;
            __align__(16) __nv_bfloat16 h[16], lo[16];
            if ((unsigned)p < 128u && (unsigned)gy < 128u && (unsigned)gx < 128u) {
                const float4* src = (const float4*)(g_buf2
                    + ((size_t)b*VOL_FULL + ((size_t)p*128 + gy)*128 + gx)*16);
                float4 q0 = src[0], q1 = src[1], q2 = src[2], q3 = src[3];
                float f[16] = {q0.x,q0.y,q0.z,q0.w, q1.x,q1.y,q1.z,q1.w,
                               q2.x,q2.y,q2.z,q2.w, q3.x,q3.y,q3.z,q3.w};
#pragma unroll
                for (int c = 0; c < 16; c++) {
                    float vv = fmaxf(fmaf(f[c], smSB[c], smSB[32 + c]), 0.f);
                    h[c] = __float2bfloat16(vv);
                    lo[c] = __float2bfloat16(vv - __bfloat162float(h[c]));
                }
            } else {
#pragma unroll
                for (int c = 0; c < 16; c++) { h[c] = __float2bfloat16(0.f); lo[c] = h[c]; }
            }
            uint32_t pb = (uint32_t)((i >> 2) & 1);
            uint32_t o0 = (uint32_t)i*32 + (pb << 4);
            uint32_t o1 = (uint32_t)i*32 + ((1u ^ pb) << 4);
            *(uint4*)(ah + o0) = *(uint4*)h;
            *(uint4*)(ah + o1) = *(uint4*)(h + 8);
            *(uint4*)(al + o0) = *(uint4*)lo;
            *(uint4*)(al + o1) = *(uint4*)(lo + 8);
        }
    };

    fillplane(2*z0 - 1);

    const int yrow = wid >> 2, xt = wid & 3;
    const int mrow = lane & 15;
    const uint32_t ahalf = (uint32_t)(lane >> 4);
    const int browl = ((lane >> 4) << 3) + (lane & 7);
    const uint32_t bhalf = (uint32_t)((lane >> 3) & 1);

    float sacc[8], qacc[8];
#pragma unroll
    for (int k = 0; k < 8; k++) { sacc[k] = 0.f; qacc[k] = 0.f; }

    for (int z = z0; z < z0 + 16; z++) {
        __syncthreads();
        fillplane(2*z);
        fillplane(2*z + 1);
        __syncthreads();

        uint32_t sb_a[3];
#pragma unroll
        for (int dz = 0; dz < 3; dz++)
            sb_a[dz] = (uint32_t)(((2*z - 1 + dz) & 3) * C3_SLOT);

        float d[4][4];
#pragma unroll
        for (int nt = 0; nt < 4; nt++)
#pragma unroll
            for (int i = 0; i < 4; i++) d[nt][i] = 0.f;

#pragma unroll
        for (int tap = 0; tap < 27; tap++) {
            const int zy = tap / 3, dx = tap % 3;
            const int dz = zy / 3, dy = zy % 3;
            int r = (2*yrow + dy)*130 + 2*(16*xt + mrow) + dx;
            uint32_t aoff = sb_a[dz] + (uint32_t)r*32
                          + ((ahalf ^ ((uint32_t)(r >> 2) & 1)) << 4);
            uint32_t ah4[4], al4[4];
            ldsm4(ah4, sb + aoff);
            ldsm4(al4, sb + C3_ALO + aoff);

#pragma unroll
            for (int gq = 0; gq < 2; gq++) {
                int br = tap*32 + gq*16 + browl;
                uint32_t boff = (uint32_t)br*32
                              + ((bhalf ^ ((uint32_t)(br >> 2) & 1)) << 4);
                uint32_t bh4[4], bl4[4];
                ldsm4(bh4, sb + C3_BHI + boff);
                ldsm4(bl4, sb + C3_BLO + boff);

                mma_bf16(d[2*gq],   ah4, bh4[0], bh4[1]);
                mma_bf16(d[2*gq+1], ah4, bh4[2], bh4[3]);
                mma_bf16(d[2*gq],   ah4, bl4[0], bl4[1]);
                mma_bf16(d[2*gq+1], ah4, bl4[2], bl4[3]);
                mma_bf16(d[2*gq],   al4, bh4[0], bh4[1]);
                mma_bf16(d[2*gq+1], al4, bh4[2], bh4[3]);
            }
        }

        const int y = y0 + yrow;
        const int xA = 16*xt + (lane >> 2);
#pragma unroll
        for (int nt = 0; nt < 4; nt++) {
            int c = 8*nt + 2*(lane & 3);
            size_t base0 = (size_t)(b*32 + c)*VOL_HALF + (size_t)z*4096 + y*64 + xA;
            g_buf3[base0]                = d[nt][0];
            g_buf3[base0 + VOL_HALF]     = d[nt][1];
            g_buf3[base0 + 8]            = d[nt][2];
            g_buf3[base0 + VOL_HALF + 8] = d[nt][3];
            sacc[2*nt]   += d[nt][0] + d[nt][2];
            sacc[2*nt+1] += d[nt][1] + d[nt][3];
            qacc[2*nt]   += d[nt][0]*d[nt][0] + d[nt][2]*d[nt][2];
            qacc[2*nt+1] += d[nt][1]*d[nt][1] + d[nt][3]*d[nt][3];
        }
    }

    __syncthreads();
    float* smS = (float*)smem;
    if (tid < 64) smS[tid] = 0.f;
    __syncthreads();
#pragma unroll
    for (int k = 0; k < 8; k++) {
        int c = 8*(k >> 1) + 2*(lane & 3) + (k & 1);
        atomicAdd(&smS[c], sacc[k]);
        atomicAdd(&smS[32 + c], qacc[k]);
    }
    __syncthreads();
    if (tid < 32) {
        int slot = (yq*4 + zs) & 63;
        atomicAdd(&g_redp[2][slot][tid],      (double)smS[tid]);
        atomicAdd(&g_redp[2][slot][32 + tid], (double)smS[32 + tid]);
    }
}

// ---------------------------------------------------------------------------
__global__ void __launch_bounds__(256) k_finalize(int stage, int C, float invN,
                                                  const float* __restrict__ g,
                                                  const float* __restrict__ b)
{
    __shared__ double sS[8][32], sQ[8][32];
    const int tid = threadIdx.x;
    const int c = tid & 31, part = tid >> 5;
    double s = 0.0, q = 0.0;
    for (int i = part; i < 64; i += 8) {
        s += g_redp[stage][i][c];
        q += g_redp[stage][i][32 + c];
    }
    sS[part][c] = s; sQ[part][c] = q;
    __syncthreads();
    if (tid < 32 && tid < C) {
        double S = 0.0, Q = 0.0;
#pragma unroll
        for (int p = 0; p < 8; p++) { S += sS[p][tid]; Q += sQ[p][tid]; }
        double mean = S * (double)invN;
        double var  = Q * (double)invN - mean*mean;
        float sc = g[tid] * rsqrtf((float)var + 1e-5f);
        g_sbt[stage][tid]      = sc;
        g_sbt[stage][32 + tid] = b[tid] - (float)mean * sc;
    }
}

// ---------------------------------------------------------------------------
__global__ void __launch_bounds__(256) k_decompW(const float* __restrict__ tok_w,
                                                 const float* __restrict__ aux_w)
{
    size_t gid = (size_t)blockIdx.x*256 + threadIdx.x;
    size_t e = gid*8;
    if (e >= (size_t)N_T*PDIM) return;
    int t = (int)(e >> 17);
    int k = (int)(e & (PDIM-1));
    const float* src = (t < 128) ? tok_w + ((size_t)t << 17) + k
                                 : aux_w + ((size_t)(t-128) << 17) + k;
    float4 a = ((const float4*)src)[0];
    float4 c = ((const float4*)src)[1];
    float v[8] = {a.x,a.y,a.z,a.w, c.x,c.y,c.z,c.w};
    __align__(16) __nv_bfloat16 h[8];
    __align__(16) __nv_bfloat16 l[8];
#pragma unroll
    for (int j = 0; j < 8; j++) {
        h[j] = __float2bfloat16(v[j]);
        l[j] = __float2bfloat16(v[j] - __bfloat162float(h[j]));
    }
    *(uint4*)(g_whi + e) = *(uint4*)h;
    *(uint4*)(g_wlo + e) = *(uint4*)l;
}

// ---------------------------------------------------------------------------
// HMMA bf16x3 patch GEMM, K-split x2, A-fill reads g_buf3 fp32 + BN2+decomp.
#define A_HI 0
#define A_LO 18432
#define B_HI 36864
#define B_LO 59904
#define GEMM_SMEM 82944

__global__ void __launch_bounds__(256, 2) k_gemm_tc()
{
    extern __shared__ __align__(16) char smem[];
    const uint32_t sb = smem_u32(smem);
    const int tile = blockIdx.x;
    const int ci = blockIdx.y >> 1, kh = blockIdx.y & 1;
    const int tid = threadIdx.x, w = tid >> 5, lane = tid & 31;

    int m = tile*128 + tid;
    bool valid = (tid < 128) && (m < 686);
    int b = 0, pz = 0, py = 0, px = 0;
    if (valid) {
        b = (m >= 343) ? 1 : 0;
        int n = m - 343*b;
        pz = n / 49; int r2 = n - 49*pz;
        py = r2 / 7; px = r2 - 7*py;
    }
    const size_t chan = (size_t)(b*32 + ci)*64;
    const float s_ = g_sbt[2][ci], b_ = g_sbt[2][32 + ci];

    const uint32_t aOff = (uint32_t)((16*w + (lane & 15))*144 + ((lane >> 4)*8)*2);
    const uint32_t aHiB = sb + A_HI + aOff;
    const uint32_t aLoB = sb + A_LO + aOff;
    const uint32_t bOff = (uint32_t)((((lane >> 4) << 3) + (lane & 7))*144
                                     + (((lane >> 3) & 1)*8)*2);
    const uint32_t bHiB = sb + B_HI + bOff;
    const uint32_t bLoB = sb + B_LO + bOff;

    float d[20][4];
#pragma unroll
    for (int nt = 0; nt < 20; nt++)
#pragma unroll
        for (int i = 0; i < 4; i++) d[nt][i] = 0.f;

    const size_t kcol = (size_t)ci*4096;

    for (int cc = 0; cc < 32; cc++) {
        const int chunk = kh*32 + cc;
        __syncthreads();

        if (tid < 128) {
            const int dz = chunk >> 2, dy0 = (chunk & 3) << 2;
#pragma unroll
            for (int j = 0; j < 4; j++) {
                __align__(16) __nv_bfloat16 h[16], lo[16];
                if (valid) {
                    const float4* src = (const float4*)(g_buf3
                        + (chan + 8*pz + dz)*4096 + (size_t)(8*py + dy0 + j)*64 + 8*px);
                    float4 q0 = src[0], q1 = src[1], q2 = src[2], q3 = src[3];
                    float f[16] = {q0.x,q0.y,q0.z,q0.w, q1.x,q1.y,q1.z,q1.w,
                                   q2.x,q2.y,q2.z,q2.w, q3.x,q3.y,q3.z,q3.w};
#pragma unroll
                    for (int c = 0; c < 16; c++) {
                        float vv = fmaxf(fmaf(f[c], s_, b_), 0.f);
                        h[c] = __float2bfloat16(vv);
                        lo[c] = __float2bfloat16(vv - __bfloat162float(h[c]));
                    }
                } else {
#pragma unroll
                    for (int c = 0; c < 16; c++) { h[c] = __float2bfloat16(0.f); lo[c] = h[c]; }
                }
                int dst = tid*144 + j*32;
                *(uint4*)(smem + A_HI + dst)      = *(uint4*)h;
                *(uint4*)(smem + A_HI + dst + 16) = *(uint4*)(h + 8);
                *(uint4*)(smem + A_LO + dst)      = *(uint4*)lo;
                *(uint4*)(smem + A_LO + dst + 16) = *(uint4*)(lo + 8);
            }
        }
        {
            const size_t kb = kcol + (size_t)chunk*64;
#pragma unroll
            for (int i = tid; i < 1280; i += 256) {
                int n = i >> 3, seg = i & 7;
                size_t so = (size_t)n*PDIM + kb + seg*8;
                int dst = n*144 + seg*16;
                *(uint4*)(smem + B_HI + dst) = *(const uint4*)(g_whi + so);
                *(uint4*)(smem + B_LO + dst) = *(const uint4*)(g_wlo + so);
            }
        }
        __syncthreads();

#pragma unroll
        for (int ks = 0; ks < 4; ks++) {
            uint32_t ah[4], al[4];
            ldsm4(ah, aHiB + ks*32);
            ldsm4(al, aLoB + ks*32);
#pragma unroll
            for (int j = 0; j < 10; j++) {
                uint32_t bh[4], bl[4];
                ldsm4(bh, bHiB + j*2304 + ks*32);
                ldsm4(bl, bLoB + j*2304 + ks*32);
                mma_bf16(d[2*j],   ah, bh[0], bh[1]);
                mma_bf16(d[2*j+1], ah, bh[2], bh[3]);
                mma_bf16(d[2*j],   ah, bl[0], bl[1]);
                mma_bf16(d[2*j+1], ah, bl[2], bl[3]);
                mma_bf16(d[2*j],   al, bh[0], bh[1]);
                mma_bf16(d[2*j+1], al, bh[2], bh[3]);
            }
        }
    }

    const int mr = tile*128 + 16*w + (lane >> 2);
    const int qc = 2*(lane & 3);
#pragma unroll
    for (int nt = 0; nt < 20; nt++) {
        int col = 8*nt + qc;
        if (mr < 686) {
            atomicAdd(&g_gemm[mr*N_T + col],     d[nt][0]);
            atomicAdd(&g_gemm[mr*N_T + col + 1], d[nt][1]);
        }
        if (mr + 8 < 686) {
            atomicAdd(&g_gemm[(mr+8)*N_T + col],     d[nt][2]);
            atomicAdd(&g_gemm[(mr+8)*N_T + col + 1], d[nt][3]);
        }
    }
}

// ---------------------------------------------------------------------------
__global__ void k_final(const float* __restrict__ tok_b,
                        const float* __restrict__ aux_b,
                        const float* __restrict__ ln_g,
                        const float* __restrict__ ln_b,
                        float* __restrict__ out)
{
    const int bn = blockIdx.x;
    const int n = bn % N_PATCH;
    const int t = threadIdx.x;

    float v = g_gemm[bn*N_T + t] + tok_b[t];
    float s = v, q = v*v;
#pragma unroll
    for (int o = 16; o; o >>= 1) {
        s += __shfl_down_sync(0xffffffffu, s, o);
        q += __shfl_down_sync(0xffffffffu, q, o);
    }
    __shared__ float ss[4], qq[4];
    int wp = t >> 5, ln = t & 31;
    if (ln == 0) { ss[wp] = s; qq[wp] = q; }
    __syncthreads();
    float S1 = ss[0] + ss[1] + ss[2] + ss[3];
    float S2 = qq[0] + qq[1] + qq[2] + qq[3];
    float mean = S1 * (1.f/128.f);
    float var  = S2 * (1.f/128.f) - mean*mean;
    float r = rsqrtf(var + 1e-5f);

    out[bn*128 + t] = (v - mean) * r * ln_g[t] + ln_b[t];

    if (t < 32)
        out[87808 + bn*32 + t] = g_gemm[bn*N_T + 128 + t] + aux_b[t];

    if (t < 3) {
        int pz = n / 49, py = (n / 7) % 7, px = n % 7;
        float c;
        if      (t == 0) c = ((float)pz * 8.f + 7.5f) * (1.f/63.f);
        else if (t == 1) c = ((float)py * 8.f + 7.5f) * (1.f/63.f);
        else             c = ((float)px * 8.f + 7.5f) * (1.f/63.f);
        out[109760 + bn*3 + t] = c;
    }
}

// ---------------------------------------------------------------------------
extern "C" void kernel_launch(void* const* d_in, const int* in_sizes, int n_in,
                              void* d_out, int out_size) {
    const float* x     = (const float*)d_in[0];
    const float* c1w   = (const float*)d_in[1];
    const float* bn1g  = (const float*)d_in[2];
    const float* bn1b  = (const float*)d_in[3];
    const float* c2w   = (const float*)d_in[4];
    const float* bn2g  = (const float*)d_in[5];
    const float* bn2b  = (const float*)d_in[6];
    const float* c3w   = (const float*)d_in[7];
    const float* bn3g  = (const float*)d_in[8];
    const float* bn3b  = (const float*)d_in[9];
    const float* tokw  = (const float*)d_in[10];
    const float* tokb  = (const float*)d_in[11];
    const float* auxw  = (const float*)d_in[12];
    const float* auxb  = (const float*)d_in[13];
    const float* lng   = (const float*)d_in[14];
    const float* lnb   = (const float*)d_in[15];
    float* out = (float*)d_out;

    cudaFuncSetAttribute(k_gemm_tc, cudaFuncAttributeMaxDynamicSharedMemorySize,
                         GEMM_SMEM);
    cudaFuncSetAttribute(k_conv2_ring2, cudaFuncAttributeMaxDynamicSharedMemorySize,
                         R2_SMEM);
    cudaFuncSetAttribute(k_conv3_ring, cudaFuncAttributeMaxDynamicSharedMemorySize,
                         C3_SMEM);

    k_zero<<<(2*N_PATCH*N_T + 255)/256, 256>>>();

    k_decompW<<<(int)(((size_t)N_T*PDIM/8 + 255)/256), 256>>>(tokw, auxw);
    k_decompW2<<<1, 256>>>(c2w);
    k_decompW3<<<1, 256>>>(c3w);

    // conv1 -> g_buf1 NHWC fp32 + stats 0
    k_conv1<<<dim3(64,128,2), 128>>>(x, c1w);
    k_finalize<<<1, 256>>>(0, 16, 1.f/(2.f*VOL_FULL), bn1g, bn1b);

    // conv2 (m64 HMMA ring) -> g_buf2 NHWC fp32 + stats 1
    k_conv2_ring2<<<dim3(32,8,2), 256, R2_SMEM>>>();
    k_finalize<<<1, 256>>>(1, 16, 1.f/(2.f*VOL_FULL), bn2g, bn2b);

    // conv3 (HMMA stride-2 ring) -> g_buf3 NCHW fp32 + stats 2
    k_conv3_ring<<<dim3(32,4,2), 256, C3_SMEM>>>();
    k_finalize<<<1, 256>>>(2, 32, 1.f/(2.f*VOL_HALF), bn3g, bn3b);

    // gemm (BN2+decomp fused A-fill; decompA deleted)
    k_gemm_tc<<<dim3(6, 64), 256, GEMM_SMEM>>>();

    k_final<<<686, 128>>>(tokb, auxb, lng, lnb, out);
}

// round 13
// speedup vs baseline: 1.0364x; 1.0364x over previous
#include <cuda_runtime.h>
#include <cuda_bf16.h>
#include <cstdint>

// ---------------------------------------------------------------------------
// InputStem R13: R11 conv2 (512-thr m32 ring, reverted) + R12 gemm with
// fused BN2+decomp A-fill (decompA deleted). conv1/conv3 unchanged.
// ---------------------------------------------------------------------------

#define VOL_FULL (128*128*128)
#define VOL_HALF (64*64*64)
#define N_PATCH  343
#define N_T      160
#define PDIM     131072

typedef unsigned long long u64;

__device__ float  g_buf1[(size_t)2*VOL_FULL*16];   // conv1 raw, NHWC fp32
__device__ float  g_buf2[(size_t)2*VOL_FULL*16];   // conv2 raw, NHWC fp32
__device__ float  g_buf3[2*32*VOL_HALF];           // conv3 raw, NCHW fp32
__device__ double g_redp[3][64][64];
__device__ float  g_sbt[3][64];
__device__ float  g_gemm[2*N_PATCH*N_T];

__device__ __nv_bfloat16 g_whi[(size_t)N_T*PDIM];
__device__ __nv_bfloat16 g_wlo[(size_t)N_T*PDIM];
__device__ __nv_bfloat16 g_w2h[6912];
__device__ __nv_bfloat16 g_w2l[6912];
__device__ __nv_bfloat16 g_w3h[13824];
__device__ __nv_bfloat16 g_w3l[13824];

__device__ __forceinline__ u64 pk2(float x, float y) {
    u64 r; asm("mov.b64 %0,{%1,%2};" : "=l"(r) : "f"(x), "f"(y)); return r;
}
__device__ __forceinline__ float2 upk(u64 v) {
    float2 r; asm("mov.b64 {%0,%1},%2;" : "=f"(r.x), "=f"(r.y) : "l"(v)); return r;
}
__device__ __forceinline__ void fma2(u64& d, u64 a, u64 b) {
    asm("fma.rn.f32x2 %0,%1,%2,%0;" : "+l"(d) : "l"(a), "l"(b));
}
__device__ __forceinline__ uint32_t smem_u32(const void* p) {
    uint32_t a;
    asm("{ .reg .u64 t; cvta.to.shared.u64 t, %1; cvt.u32.u64 %0, t; }" : "=r"(a) : "l"(p));
    return a;
}
__device__ __forceinline__ void ldsm4(uint32_t* r, uint32_t addr) {
    asm volatile("ldmatrix.sync.aligned.m8n8.x4.shared.b16 {%0,%1,%2,%3}, [%4];"
        : "=r"(r[0]), "=r"(r[1]), "=r"(r[2]), "=r"(r[3]) : "r"(addr));
}
__device__ __forceinline__ void mma_bf16(float* d, const uint32_t* a,
                                         uint32_t b0, uint32_t b1) {
    asm volatile("mma.sync.aligned.m16n8k16.row.col.f32.bf16.bf16.f32 "
        "{%0,%1,%2,%3}, {%4,%5,%6,%7}, {%8,%9}, {%0,%1,%2,%3};"
        : "+f"(d[0]), "+f"(d[1]), "+f"(d[2]), "+f"(d[3])
        : "r"(a[0]), "r"(a[1]), "r"(a[2]), "r"(a[3]), "r"(b0), "r"(b1));
}

// ---------------------------------------------------------------------------
__global__ void k_zero() {
    int i = blockIdx.x * blockDim.x + threadIdx.x;
    if (i < 2*N_PATCH*N_T) g_gemm[i] = 0.f;
    if (i < 3*64*64) ((double*)g_redp)[i] = 0.0;
}

// ---------------------------------------------------------------------------
// conv1: 1->16, FFMA2, TWO y-rows; NHWC fp32 out via smem staging; stats 0.
__global__ void __launch_bounds__(128) k_conv1(const float* __restrict__ in,
                                               const float* __restrict__ w)
{
    __shared__ __align__(16) float sm_in[13*128];
    __shared__ float sm_w[27*16];
    __shared__ __align__(16) float sm_out[2*16*132];
    const int y0 = 2*blockIdx.x, z = blockIdx.y, b = blockIdx.z;
    const int t = threadIdx.x, l = t & 31, g = t >> 5;

    for (int i = t; i < 27*16; i += 128) {
        int co = i & 15, k = i >> 4;
        sm_w[i] = w[co*27 + k];
    }
    {
        const float* inc = in + (size_t)b * VOL_FULL;
#pragma unroll
        for (int j = 0; j < 13; j++) {
            int i = t + 128*j;
            float v = 0.f;
            if (i < 1584) {
                int r = i / 132, idx = i - 132*r;
                int gz = z - 1 + (r >> 2), gy = y0 - 1 + (r & 3), gx = idx - 1;
                if ((unsigned)gz < 128u && (unsigned)gy < 128u && (unsigned)gx < 128u)
                    v = inc[(gz*128 + gy)*128 + gx];
            }
            if (i < 13*128) sm_in[i] = v;
        }
    }
    __syncthreads();

    u64 acc[2][2][4];
#pragma unroll
    for (int yr = 0; yr < 2; yr++)
#pragma unroll
        for (int j2 = 0; j2 < 2; j2++)
#pragma unroll
            for (int xx = 0; xx < 4; xx++) acc[yr][j2][xx] = 0ULL;

#pragma unroll
    for (int r = 0; r < 12; r++) {
        float4 A = *(const float4*)(sm_in + r*132 + 4*l);
        float4 B = *(const float4*)(sm_in + r*132 + 4*l + 4);
        float a[7] = {A.x, A.y, A.z, A.w, B.x, B.y, B.z};
        u64 pv[7];
#pragma unroll
        for (int j = 0; j < 7; j++) pv[j] = pk2(a[j], a[j]);
        const int dz = r >> 2, m = r & 3;
#pragma unroll
        for (int yr = 0; yr < 2; yr++) {
            const int dyy = m - yr;
            if (dyy < 0 || dyy > 2) continue;
            const int kb = dz*9 + dyy*3;
#pragma unroll
            for (int dx = 0; dx < 3; dx++) {
                u64 w0 = *(const u64*)(sm_w + (kb+dx)*16 + g*4);
                u64 w1 = *(const u64*)(sm_w + (kb+dx)*16 + g*4 + 2);
#pragma unroll
                for (int xx = 0; xx < 4; xx++) {
                    fma2(acc[yr][0][xx], pv[dx+xx], w0);
                    fma2(acc[yr][1][xx], pv[dx+xx], w1);
                }
            }
        }
    }

    float2 v[2][2][4];
#pragma unroll
    for (int yr = 0; yr < 2; yr++)
#pragma unroll
        for (int j2 = 0; j2 < 2; j2++)
#pragma unroll
            for (int xx = 0; xx < 4; xx++) v[yr][j2][xx] = upk(acc[yr][j2][xx]);

#pragma unroll
    for (int yr = 0; yr < 2; yr++)
#pragma unroll
        for (int j2 = 0; j2 < 2; j2++) {
            int co = g*4 + 2*j2;
#pragma unroll
            for (int xx = 0; xx < 4; xx++) {
                sm_out[(yr*16 + co)*132 + 4*l + xx]   = v[yr][j2][xx].x;
                sm_out[(yr*16 + co+1)*132 + 4*l + xx] = v[yr][j2][xx].y;
            }
        }
    __syncthreads();

#pragma unroll
    for (int p = 0; p < 2; p++) {
        int vox = t + 128*p;
        int yr = vox >> 7, x = vox & 127;
        float o[16];
#pragma unroll
        for (int c = 0; c < 16; c++) o[c] = sm_out[(yr*16 + c)*132 + x];
        float* dst = g_buf1 + ((size_t)b*VOL_FULL + ((size_t)z*128 + y0 + yr)*128 + x)*16;
        *(float4*)(dst)      = make_float4(o[0], o[1], o[2], o[3]);
        *(float4*)(dst + 4)  = make_float4(o[4], o[5], o[6], o[7]);
        *(float4*)(dst + 8)  = make_float4(o[8], o[9], o[10], o[11]);
        *(float4*)(dst + 12) = make_float4(o[12], o[13], o[14], o[15]);
    }

#pragma unroll
    for (int c = 0; c < 4; c++) {
        float s = 0.f, q = 0.f;
#pragma unroll
        for (int yr = 0; yr < 2; yr++)
#pragma unroll
            for (int xx = 0; xx < 4; xx++) {
                float val = (c & 1) ? v[yr][c>>1][xx].y : v[yr][c>>1][xx].x;
                s += val; q = fmaf(val, val, q);
            }
#pragma unroll
        for (int o = 16; o; o >>= 1) {
            s += __shfl_down_sync(0xffffffffu, s, o);
            q += __shfl_down_sync(0xffffffffu, q, o);
        }
        if (l == 0) {
            atomicAdd(&g_redp[0][z & 63][g*4 + c],      (double)s);
            atomicAdd(&g_redp[0][z & 63][32 + g*4 + c], (double)q);
        }
    }
}

// ---------------------------------------------------------------------------
__global__ void k_decompW2(const float* __restrict__ w) {
    for (int i = threadIdx.x; i < 6912; i += 256) {
        int ci = i & 15, co = (i >> 4) & 15, tap = i >> 8;
        float v = w[(co*16 + ci)*27 + tap];
        __nv_bfloat16 h = __float2bfloat16(v);
        g_w2h[i] = h;
        g_w2l[i] = __float2bfloat16(v - __bfloat162float(h));
    }
}
__global__ void k_decompW3(const float* __restrict__ w) {
    for (int i = threadIdx.x; i < 13824; i += 256) {
        int ci = i & 15, co = (i >> 4) & 31, tap = i >> 9;
        float v = w[(co*16 + ci)*27 + tap];
        __nv_bfloat16 h = __float2bfloat16(v);
        g_w3h[i] = h;
        g_w3l[i] = __float2bfloat16(v - __bfloat162float(h));
    }
}

// ---------------------------------------------------------------------------
// conv2 ring2 (R11): 4 y-rows, 16 z, 512 thr / 16 warps, warp = m32.
#define R2_SLOT   24960
#define R2_ALO    99840
#define R2_BHI    199680
#define R2_BLO    213504
#define R2_SB     227328
#define R2_SMEM   227584

__global__ void __launch_bounds__(512, 1) k_conv2_ring2()
{
    extern __shared__ __align__(16) char smem[];
    const uint32_t sb = smem_u32(smem);
    float* smSB = (float*)(smem + R2_SB);
    const int yq = blockIdx.x, zs = blockIdx.y, b = blockIdx.z;
    const int y0 = 4*yq, z0 = 16*zs;
    const int tid = threadIdx.x, wid = tid >> 5, lane = tid & 31;

    if (tid < 64) smSB[tid] = g_sbt[0][tid];

    for (int i = tid; i < 864; i += 512) {
        int row = i >> 1, hf = i & 1;
        uint4 vh = *(const uint4*)(g_w2h + row*16 + hf*8);
        uint4 vl = *(const uint4*)(g_w2l + row*16 + hf*8);
        uint32_t off = (uint32_t)row*32 + (((uint32_t)hf ^ ((uint32_t)(row>>2)&1)) << 4);
        *(uint4*)(smem + R2_BHI + off) = vh;
        *(uint4*)(smem + R2_BLO + off) = vl;
    }
    __syncthreads();

    auto fillplane = [&](int p) {
        int slot = (p & 3);
        char* ah = smem + slot*R2_SLOT;
        char* al = smem + R2_ALO + slot*R2_SLOT;
        for (int i = tid; i < 780; i += 512) {
            int dyr = i / 130, xs = i - dyr*130;
            int gx = xs - 1, gy = y0 - 1 + dyr;
            __align__(16) __nv_bfloat16 h[16], lo[16];
            if ((unsigned)p < 128u && (unsigned)gy < 128u && (unsigned)gx < 128u) {
                const float4* src = (const float4*)(g_buf1
                    + ((size_t)b*VOL_FULL + ((size_t)p*128 + gy)*128 + gx)*16);
                float4 q0 = src[0], q1 = src[1], q2 = src[2], q3 = src[3];
                float f[16] = {q0.x,q0.y,q0.z,q0.w, q1.x,q1.y,q1.z,q1.w,
                               q2.x,q2.y,q2.z,q2.w, q3.x,q3.y,q3.z,q3.w};
#pragma unroll
                for (int c = 0; c < 16; c++) {
                    float vv = fmaxf(fmaf(f[c], smSB[c], smSB[32 + c]), 0.f);
                    h[c] = __float2bfloat16(vv);
                    lo[c] = __float2bfloat16(vv - __bfloat162float(h[c]));
                }
            } else {
#pragma unroll
                for (int c = 0; c < 16; c++) { h[c] = __float2bfloat16(0.f); lo[c] = h[c]; }
            }
            uint32_t pb = (uint32_t)((i >> 2) & 1);
            uint32_t o0 = (uint32_t)i*32 + (pb << 4);
            uint32_t o1 = (uint32_t)i*32 + ((1u ^ pb) << 4);
            *(uint4*)(ah + o0) = *(uint4*)h;
            *(uint4*)(ah + o1) = *(uint4*)(h + 8);
            *(uint4*)(al + o0) = *(uint4*)lo;
            *(uint4*)(al + o1) = *(uint4*)(lo + 8);
        }
    };

    fillplane(z0 - 1);
    fillplane(z0);

    const int yr = wid >> 2, xt = wid & 3;
    const int mrow = lane & 15;
    const uint32_t ahalf = (uint32_t)(lane >> 4);
    const int browl = ((lane >> 4) << 3) + (lane & 7);
    const uint32_t bhalf = (uint32_t)((lane >> 3) & 1);

    float sacc[4] = {0.f,0.f,0.f,0.f}, qacc[4] = {0.f,0.f,0.f,0.f};

    for (int z = z0; z < z0 + 16; z++) {
        fillplane(z + 1);
        __syncthreads();

        uint32_t sb_a[3];
#pragma unroll
        for (int dz = 0; dz < 3; dz++)
            sb_a[dz] = (uint32_t)(((z - 1 + dz) & 3) * R2_SLOT);

        float d[2][2][4];
#pragma unroll
        for (int mt = 0; mt < 2; mt++)
#pragma unroll
            for (int nt = 0; nt < 2; nt++)
#pragma unroll
                for (int i = 0; i < 4; i++) d[mt][nt][i] = 0.f;

#pragma unroll
        for (int tap = 0; tap < 27; tap++) {
            const int zy = tap / 3, dx = tap % 3;
            const int dz = zy / 3, dy = zy % 3;
            const int rbase = (yr + dy)*130 + 32*xt + dx + mrow;

            uint32_t ah0[4], al0[4], ah1[4], al1[4];
            {
                int r = rbase;
                uint32_t aoff = sb_a[dz] + (uint32_t)r*32
                              + ((ahalf ^ ((uint32_t)(r >> 2) & 1)) << 4);
                ldsm4(ah0, sb + aoff);
                ldsm4(al0, sb + R2_ALO + aoff);
            }
            {
                int r = rbase + 16;
                uint32_t aoff = sb_a[dz] + (uint32_t)r*32
                              + ((ahalf ^ ((uint32_t)(r >> 2) & 1)) << 4);
                ldsm4(ah1, sb + aoff);
                ldsm4(al1, sb + R2_ALO + aoff);
            }

            int br = tap*16 + browl;
            uint32_t boff = (uint32_t)br*32
                          + ((bhalf ^ ((uint32_t)(br >> 2) & 1)) << 4);
            uint32_t bh4[4], bl4[4];
            ldsm4(bh4, sb + R2_BHI + boff);
            ldsm4(bl4, sb + R2_BLO + boff);

            mma_bf16(d[0][0], ah0, bh4[0], bh4[1]);
            mma_bf16(d[0][1], ah0, bh4[2], bh4[3]);
            mma_bf16(d[0][0], ah0, bl4[0], bl4[1]);
            mma_bf16(d[0][1], ah0, bl4[2], bl4[3]);
            mma_bf16(d[0][0], al0, bh4[0], bh4[1]);
            mma_bf16(d[0][1], al0, bh4[2], bh4[3]);

            mma_bf16(d[1][0], ah1, bh4[0], bh4[1]);
            mma_bf16(d[1][1], ah1, bh4[2], bh4[3]);
            mma_bf16(d[1][0], ah1, bl4[0], bl4[1]);
            mma_bf16(d[1][1], ah1, bl4[2], bl4[3]);
            mma_bf16(d[1][0], al1, bh4[0], bh4[1]);
            mma_bf16(d[1][1], al1, bh4[2], bh4[3]);
        }

        // NHWC stores + running stats
#pragma unroll
        for (int mt = 0; mt < 2; mt++) {
            int x = 32*xt + 16*mt + (lane >> 2);
            size_t vbase = ((size_t)b*VOL_FULL + ((size_t)z*128 + y0 + yr)*128 + x)*16;
#pragma unroll
            for (int nt = 0; nt < 2; nt++) {
                int c = 8*nt + 2*(lane & 3);
                *(float2*)(g_buf2 + vbase + c)       = make_float2(d[mt][nt][0], d[mt][nt][1]);
                *(float2*)(g_buf2 + vbase + 128 + c) = make_float2(d[mt][nt][2], d[mt][nt][3]);
                sacc[2*nt]   += d[mt][nt][0] + d[mt][nt][2];
                sacc[2*nt+1] += d[mt][nt][1] + d[mt][nt][3];
                qacc[2*nt]   += d[mt][nt][0]*d[mt][nt][0] + d[mt][nt][2]*d[mt][nt][2];
                qacc[2*nt+1] += d[mt][nt][1]*d[mt][nt][1] + d[mt][nt][3]*d[mt][nt][3];
            }
        }
    }

    __syncthreads();
    float* smS = (float*)smem;
    if (tid < 32) smS[tid] = 0.f;
    __syncthreads();
#pragma unroll
    for (int k = 0; k < 4; k++) {
        int c = 8*(k >> 1) + 2*(lane & 3) + (k & 1);
        atomicAdd(&smS[c], sacc[k]);
        atomicAdd(&smS[16 + c], qacc[k]);
    }
    __syncthreads();
    if (tid < 16) {
        int slot = (yq*8 + zs) & 63;
        atomicAdd(&g_redp[1][slot][tid],      (double)smS[tid]);
        atomicAdd(&g_redp[1][slot][32 + tid], (double)smS[16 + tid]);
    }
}

// ---------------------------------------------------------------------------
// conv3 ring (R11): stride-2 16->32 HMMA bf16x3.
#define C3_SLOT 20800
#define C3_ALO  83200
#define C3_BHI  166400
#define C3_BLO  194048
#define C3_SB   221696
#define C3_SMEM 221952

__global__ void __launch_bounds__(256, 1) k_conv3_ring()
{
    extern __shared__ __align__(16) char smem[];
    const uint32_t sb = smem_u32(smem);
    float* smSB = (float*)(smem + C3_SB);
    const int yq = blockIdx.x, zs = blockIdx.y, b = blockIdx.z;
    const int y0 = 2*yq, z0 = 16*zs;
    const int tid = threadIdx.x, wid = tid >> 5, lane = tid & 31;

    if (tid < 64) smSB[tid] = g_sbt[1][tid];

    for (int i = tid; i < 1728; i += 256) {
        int row = i >> 1, hf = i & 1;
        uint4 vh = *(const uint4*)(g_w3h + row*16 + hf*8);
        uint4 vl = *(const uint4*)(g_w3l + row*16 + hf*8);
        uint32_t off = (uint32_t)row*32 + (((uint32_t)hf ^ ((uint32_t)(row>>2)&1)) << 4);
        *(uint4*)(smem + C3_BHI + off) = vh;
        *(uint4*)(smem + C3_BLO + off) = vl;
    }
    __syncthreads();

    auto fillplane = [&](int p) {
        int slot = (p & 3);
        char* ah = smem + slot*C3_SLOT;
        char* al = smem + C3_ALO + slot*C3_SLOT;
        for (int i = tid; i < 650; i += 256) {
            int dyr = i / 130, xs = i - dyr*130;
            int gx = xs - 1, gy = 2*y0 - 1 + dyr;
            __align__(16) __nv_bfloat16 h[16], lo[16];
            if ((unsigned)p < 128u && (unsigned)gy < 128u && (unsigned)gx < 128u) {
                const float4* src = (const float4*)(g_buf2
                    + ((size_t)b*VOL_FULL + ((size_t)p*128 + gy)*128 + gx)*16);
                float4 q0 = src[0], q1 = src[1], q2 = src[2], q3 = src[3];
                float f[16] = {q0.x,q0.y,q0.z,q0.w, q1.x,q1.y,q1.z,q1.w,
                               q2.x,q2.y,q2.z,q2.w, q3.x,q3.y,q3.z,q3.w};
#pragma unroll
                for (int c = 0; c < 16; c++) {
                    float vv = fmaxf(fmaf(f[c], smSB[c], smSB[32 + c]), 0.f);
                    h[c] = __float2bfloat16(vv);
                    lo[c] = __float2bfloat16(vv - __bfloat162float(h[c]));
                }
            } else {
#pragma unroll
                for (int c = 0; c < 16; c++) { h[c] = __float2bfloat16(0.f); lo[c] = h[c]; }
            }
            uint32_t pb = (uint32_t)((i >> 2) & 1);
            uint32_t o0 = (uint32_t)i*32 + (pb << 4);
            uint32_t o1 = (uint32_t)i*32 + ((1u ^ pb) << 4);
            *(uint4*)(ah + o0) = *(uint4*)h;
            *(uint4*)(ah + o1) = *(uint4*)(h + 8);
            *(uint4*)(al + o0) = *(uint4*)lo;
            *(uint4*)(al + o1) = *(uint4*)(lo + 8);
        }
    };

    fillplane(2*z0 - 1);

    const int yrow = wid >> 2, xt = wid & 3;
    const int mrow = lane & 15;
    const uint32_t ahalf = (uint32_t)(lane >> 4);
    const int browl = ((lane >> 4) << 3) + (lane & 7);
    const uint32_t bhalf = (uint32_t)((lane >> 3) & 1);

    float sacc[8], qacc[8];
#pragma unroll
    for (int k = 0; k < 8; k++) { sacc[k] = 0.f; qacc[k] = 0.f; }

    for (int z = z0; z < z0 + 16; z++) {
        __syncthreads();
        fillplane(2*z);
        fillplane(2*z + 1);
        __syncthreads();

        uint32_t sb_a[3];
#pragma unroll
        for (int dz = 0; dz < 3; dz++)
            sb_a[dz] = (uint32_t)(((2*z - 1 + dz) & 3) * C3_SLOT);

        float d[4][4];
#pragma unroll
        for (int nt = 0; nt < 4; nt++)
#pragma unroll
            for (int i = 0; i < 4; i++) d[nt][i] = 0.f;

#pragma unroll
        for (int tap = 0; tap < 27; tap++) {
            const int zy = tap / 3, dx = tap % 3;
            const int dz = zy / 3, dy = zy % 3;
            int r = (2*yrow + dy)*130 + 2*(16*xt + mrow) + dx;
            uint32_t aoff = sb_a[dz] + (uint32_t)r*32
                          + ((ahalf ^ ((uint32_t)(r >> 2) & 1)) << 4);
            uint32_t ah4[4], al4[4];
            ldsm4(ah4, sb + aoff);
            ldsm4(al4, sb + C3_ALO + aoff);

#pragma unroll
            for (int gq = 0; gq < 2; gq++) {
                int br = tap*32 + gq*16 + browl;
                uint32_t boff = (uint32_t)br*32
                              + ((bhalf ^ ((uint32_t)(br >> 2) & 1)) << 4);
                uint32_t bh4[4], bl4[4];
                ldsm4(bh4, sb + C3_BHI + boff);
                ldsm4(bl4, sb + C3_BLO + boff);

                mma_bf16(d[2*gq],   ah4, bh4[0], bh4[1]);
                mma_bf16(d[2*gq+1], ah4, bh4[2], bh4[3]);
                mma_bf16(d[2*gq],   ah4, bl4[0], bl4[1]);
                mma_bf16(d[2*gq+1], ah4, bl4[2], bl4[3]);
                mma_bf16(d[2*gq],   al4, bh4[0], bh4[1]);
                mma_bf16(d[2*gq+1], al4, bh4[2], bh4[3]);
            }
        }

        const int y = y0 + yrow;
        const int xA = 16*xt + (lane >> 2);
#pragma unroll
        for (int nt = 0; nt < 4; nt++) {
            int c = 8*nt + 2*(lane & 3);
            size_t base0 = (size_t)(b*32 + c)*VOL_HALF + (size_t)z*4096 + y*64 + xA;
            g_buf3[base0]                = d[nt][0];
            g_buf3[base0 + VOL_HALF]     = d[nt][1];
            g_buf3[base0 + 8]            = d[nt][2];
            g_buf3[base0 + VOL_HALF + 8] = d[nt][3];
            sacc[2*nt]   += d[nt][0] + d[nt][2];
            sacc[2*nt+1] += d[nt][1] + d[nt][3];
            qacc[2*nt]   += d[nt][0]*d[nt][0] + d[nt][2]*d[nt][2];
            qacc[2*nt+1] += d[nt][1]*d[nt][1] + d[nt][3]*d[nt][3];
        }
    }

    __syncthreads();
    float* smS = (float*)smem;
    if (tid < 64) smS[tid] = 0.f;
    __syncthreads();
#pragma unroll
    for (int k = 0; k < 8; k++) {
        int c = 8*(k >> 1) + 2*(lane & 3) + (k & 1);
        atomicAdd(&smS[c], sacc[k]);
        atomicAdd(&smS[32 + c], qacc[k]);
    }
    __syncthreads();
    if (tid < 32) {
        int slot = (yq*4 + zs) & 63;
        atomicAdd(&g_redp[2][slot][tid],      (double)smS[tid]);
        atomicAdd(&g_redp[2][slot][32 + tid], (double)smS[32 + tid]);
    }
}

// ---------------------------------------------------------------------------
__global__ void __launch_bounds__(256) k_finalize(int stage, int C, float invN,
                                                  const float* __restrict__ g,
                                                  const float* __restrict__ b)
{
    __shared__ double sS[8][32], sQ[8][32];
    const int tid = threadIdx.x;
    const int c = tid & 31, part = tid >> 5;
    double s = 0.0, q = 0.0;
    for (int i = part; i < 64; i += 8) {
        s += g_redp[stage][i][c];
        q += g_redp[stage][i][32 + c];
    }
    sS[part][c] = s; sQ[part][c] = q;
    __syncthreads();
    if (tid < 32 && tid < C) {
        double S = 0.0, Q = 0.0;
#pragma unroll
        for (int p = 0; p < 8; p++) { S += sS[p][tid]; Q += sQ[p][tid]; }
        double mean = S * (double)invN;
        double var  = Q * (double)invN - mean*mean;
        float sc = g[tid] * rsqrtf((float)var + 1e-5f);
        g_sbt[stage][tid]      = sc;
        g_sbt[stage][32 + tid] = b[tid] - (float)mean * sc;
    }
}

// ---------------------------------------------------------------------------
__global__ void __launch_bounds__(256) k_decompW(const float* __restrict__ tok_w,
                                                 const float* __restrict__ aux_w)
{
    size_t gid = (size_t)blockIdx.x*256 + threadIdx.x;
    size_t e = gid*8;
    if (e >= (size_t)N_T*PDIM) return;
    int t = (int)(e >> 17);
    int k = (int)(e & (PDIM-1));
    const float* src = (t < 128) ? tok_w + ((size_t)t << 17) + k
                                 : aux_w + ((size_t)(t-128) << 17) + k;
    float4 a = ((const float4*)src)[0];
    float4 c = ((const float4*)src)[1];
    float v[8] = {a.x,a.y,a.z,a.w, c.x,c.y,c.z,c.w};
    __align__(16) __nv_bfloat16 h[8];
    __align__(16) __nv_bfloat16 l[8];
#pragma unroll
    for (int j = 0; j < 8; j++) {
        h[j] = __float2bfloat16(v[j]);
        l[j] = __float2bfloat16(v[j] - __bfloat162float(h[j]));
    }
    *(uint4*)(g_whi + e) = *(uint4*)h;
    *(uint4*)(g_wlo + e) = *(uint4*)l;
}

// ---------------------------------------------------------------------------
// HMMA bf16x3 patch GEMM, K-split x2, A-fill reads g_buf3 fp32 + BN2+decomp.
#define A_HI 0
#define A_LO 18432
#define B_HI 36864
#define B_LO 59904
#define GEMM_SMEM 82944

__global__ void __launch_bounds__(256, 2) k_gemm_tc()
{
    extern __shared__ __align__(16) char smem[];
    const uint32_t sb = smem_u32(smem);
    const int tile = blockIdx.x;
    const int ci = blockIdx.y >> 1, kh = blockIdx.y & 1;
    const int tid = threadIdx.x, w = tid >> 5, lane = tid & 31;

    int m = tile*128 + tid;
    bool valid = (tid < 128) && (m < 686);
    int b = 0, pz = 0, py = 0, px = 0;
    if (valid) {
        b = (m >= 343) ? 1 : 0;
        int n = m - 343*b;
        pz = n / 49; int r2 = n - 49*pz;
        py = r2 / 7; px = r2 - 7*py;
    }
    const size_t chan = (size_t)(b*32 + ci)*64;
    const float s_ = g_sbt[2][ci], b_ = g_sbt[2][32 + ci];

    const uint32_t aOff = (uint32_t)((16*w + (lane & 15))*144 + ((lane >> 4)*8)*2);
    const uint32_t aHiB = sb + A_HI + aOff;
    const uint32_t aLoB = sb + A_LO + aOff;
    const uint32_t bOff = (uint32_t)((((lane >> 4) << 3) + (lane & 7))*144
                                     + (((lane >> 3) & 1)*8)*2);
    const uint32_t bHiB = sb + B_HI + bOff;
    const uint32_t bLoB = sb + B_LO + bOff;

    float d[20][4];
#pragma unroll
    for (int nt = 0; nt < 20; nt++)
#pragma unroll
        for (int i = 0; i < 4; i++) d[nt][i] = 0.f;

    const size_t kcol = (size_t)ci*4096;

    for (int cc = 0; cc < 32; cc++) {
        const int chunk = kh*32 + cc;
        __syncthreads();

        if (tid < 128) {
            const int dz = chunk >> 2, dy0 = (chunk & 3) << 2;
#pragma unroll
            for (int j = 0; j < 4; j++) {
                __align__(16) __nv_bfloat16 h[16], lo[16];
                if (valid) {
                    const float4* src = (const float4*)(g_buf3
                        + (chan + 8*pz + dz)*4096 + (size_t)(8*py + dy0 + j)*64 + 8*px);
                    float4 q0 = src[0], q1 = src[1], q2 = src[2], q3 = src[3];
                    float f[16] = {q0.x,q0.y,q0.z,q0.w, q1.x,q1.y,q1.z,q1.w,
                                   q2.x,q2.y,q2.z,q2.w, q3.x,q3.y,q3.z,q3.w};
#pragma unroll
                    for (int c = 0; c < 16; c++) {
                        float vv = fmaxf(fmaf(f[c], s_, b_), 0.f);
                        h[c] = __float2bfloat16(vv);
                        lo[c] = __float2bfloat16(vv - __bfloat162float(h[c]));
                    }
                } else {
#pragma unroll
                    for (int c = 0; c < 16; c++) { h[c] = __float2bfloat16(0.f); lo[c] = h[c]; }
                }
                int dst = tid*144 + j*32;
                *(uint4*)(smem + A_HI + dst)      = *(uint4*)h;
                *(uint4*)(smem + A_HI + dst + 16) = *(uint4*)(h + 8);
                *(uint4*)(smem + A_LO + dst)      = *(uint4*)lo;
                *(uint4*)(smem + A_LO + dst + 16) = *(uint4*)(lo + 8);
            }
        }
        {
            const size_t kb = kcol + (size_t)chunk*64;
#pragma unroll
            for (int i = tid; i < 1280; i += 256) {
                int n = i >> 3, seg = i & 7;
                size_t so = (size_t)n*PDIM + kb + seg*8;
                int dst = n*144 + seg*16;
                *(uint4*)(smem + B_HI + dst) = *(const uint4*)(g_whi + so);
                *(uint4*)(smem + B_LO + dst) = *(const uint4*)(g_wlo + so);
            }
        }
        __syncthreads();

#pragma unroll
        for (int ks = 0; ks < 4; ks++) {
            uint32_t ah[4], al[4];
            ldsm4(ah, aHiB + ks*32);
            ldsm4(al, aLoB + ks*32);
#pragma unroll
            for (int j = 0; j < 10; j++) {
                uint32_t bh[4], bl[4];
                ldsm4(bh, bHiB + j*2304 + ks*32);
                ldsm4(bl, bLoB + j*2304 + ks*32);
                mma_bf16(d[2*j],   ah, bh[0], bh[1]);
                mma_bf16(d[2*j+1], ah, bh[2], bh[3]);
                mma_bf16(d[2*j],   ah, bl[0], bl[1]);
                mma_bf16(d[2*j+1], ah, bl[2], bl[3]);
                mma_bf16(d[2*j],   al, bh[0], bh[1]);
                mma_bf16(d[2*j+1], al, bh[2], bh[3]);
            }
        }
    }

    const int mr = tile*128 + 16*w + (lane >> 2);
    const int qc = 2*(lane & 3);
#pragma unroll
    for (int nt = 0; nt < 20; nt++) {
        int col = 8*nt + qc;
        if (mr < 686) {
            atomicAdd(&g_gemm[mr*N_T + col],     d[nt][0]);
            atomicAdd(&g_gemm[mr*N_T + col + 1], d[nt][1]);
        }
        if (mr + 8 < 686) {
            atomicAdd(&g_gemm[(mr+8)*N_T + col],     d[nt][2]);
            atomicAdd(&g_gemm[(mr+8)*N_T + col + 1], d[nt][3]);
        }
    }
}

// ---------------------------------------------------------------------------
__global__ void k_final(const float* __restrict__ tok_b,
                        const float* __restrict__ aux_b,
                        const float* __restrict__ ln_g,
                        const float* __restrict__ ln_b,
                        float* __restrict__ out)
{
    const int bn = blockIdx.x;
    const int n = bn % N_PATCH;
    const int t = threadIdx.x;

    float v = g_gemm[bn*N_T + t] + tok_b[t];
    float s = v, q = v*v;
#pragma unroll
    for (int o = 16; o; o >>= 1) {
        s += __shfl_down_sync(0xffffffffu, s, o);
        q += __shfl_down_sync(0xffffffffu, q, o);
    }
    __shared__ float ss[4], qq[4];
    int wp = t >> 5, ln = t & 31;
    if (ln == 0) { ss[wp] = s; qq[wp] = q; }
    __syncthreads();
    float S1 = ss[0] + ss[1] + ss[2] + ss[3];
    float S2 = qq[0] + qq[1] + qq[2] + qq[3];
    float mean = S1 * (1.f/128.f);
    float var  = S2 * (1.f/128.f) - mean*mean;
    float r = rsqrtf(var + 1e-5f);

    out[bn*128 + t] = (v - mean) * r * ln_g[t] + ln_b[t];

    if (t < 32)
        out[87808 + bn*32 + t] = g_gemm[bn*N_T + 128 + t] + aux_b[t];

    if (t < 3) {
        int pz = n / 49, py = (n / 7) % 7, px = n % 7;
        float c;
        if      (t == 0) c = ((float)pz * 8.f + 7.5f) * (1.f/63.f);
        else if (t == 1) c = ((float)py * 8.f + 7.5f) * (1.f/63.f);
        else             c = ((float)px * 8.f + 7.5f) * (1.f/63.f);
        out[109760 + bn*3 + t] = c;
    }
}

// ---------------------------------------------------------------------------
extern "C" void kernel_launch(void* const* d_in, const int* in_sizes, int n_in,
                              void* d_out, int out_size) {
    const float* x     = (const float*)d_in[0];
    const float* c1w   = (const float*)d_in[1];
    const float* bn1g  = (const float*)d_in[2];
    const float* bn1b  = (const float*)d_in[3];
    const float* c2w   = (const float*)d_in[4];
    const float* bn2g  = (const float*)d_in[5];
    const float* bn2b  = (const float*)d_in[6];
    const float* c3w   = (const float*)d_in[7];
    const float* bn3g  = (const float*)d_in[8];
    const float* bn3b  = (const float*)d_in[9];
    const float* tokw  = (const float*)d_in[10];
    const float* tokb  = (const float*)d_in[11];
    const float* auxw  = (const float*)d_in[12];
    const float* auxb  = (const float*)d_in[13];
    const float* lng   = (const float*)d_in[14];
    const float* lnb   = (const float*)d_in[15];
    float* out = (float*)d_out;

    cudaFuncSetAttribute(k_gemm_tc, cudaFuncAttributeMaxDynamicSharedMemorySize,
                         GEMM_SMEM);
    cudaFuncSetAttribute(k_conv2_ring2, cudaFuncAttributeMaxDynamicSharedMemorySize,
                         R2_SMEM);
    cudaFuncSetAttribute(k_conv3_ring, cudaFuncAttributeMaxDynamicSharedMemorySize,
                         C3_SMEM);

    k_zero<<<(2*N_PATCH*N_T + 255)/256, 256>>>();

    k_decompW<<<(int)(((size_t)N_T*PDIM/8 + 255)/256), 256>>>(tokw, auxw);
    k_decompW2<<<1, 256>>>(c2w);
    k_decompW3<<<1, 256>>>(c3w);

    // conv1 -> g_buf1 NHWC fp32 + stats 0
    k_conv1<<<dim3(64,128,2), 128>>>(x, c1w);
    k_finalize<<<1, 256>>>(0, 16, 1.f/(2.f*VOL_FULL), bn1g, bn1b);

    // conv2 (512-thr m32 HMMA ring) -> g_buf2 NHWC fp32 + stats 1
    k_conv2_ring2<<<dim3(32,8,2), 512, R2_SMEM>>>();
    k_finalize<<<1, 256>>>(1, 16, 1.f/(2.f*VOL_FULL), bn2g, bn2b);

    // conv3 (HMMA stride-2 ring) -> g_buf3 NCHW fp32 + stats 2
    k_conv3_ring<<<dim3(32,4,2), 256, C3_SMEM>>>();
    k_finalize<<<1, 256>>>(2, 32, 1.f/(2.f*VOL_HALF), bn3g, bn3b);

    // gemm (BN2+decomp fused A-fill; decompA deleted)
    k_gemm_tc<<<dim3(6, 64), 256, GEMM_SMEM>>>();

    k_final<<<686, 128>>>(tokb, auxb, lng, lnb, out);
}

// round 14
// speedup vs baseline: 1.0594x; 1.0222x over previous
#include <cuda_runtime.h>
#include <cuda_bf16.h>
#include <cstdint>

// ---------------------------------------------------------------------------
// InputStem R14: R11 pipeline (separate decompA restored) + gemm warp re-tile
// m32 x n80 (B-ldsm halved) + merged decompW2/W3.
// ---------------------------------------------------------------------------

#define VOL_FULL (128*128*128)
#define VOL_HALF (64*64*64)
#define N_PATCH  343
#define N_T      160
#define PDIM     131072

typedef unsigned long long u64;

__device__ float  g_buf1[(size_t)2*VOL_FULL*16];   // conv1 raw, NHWC fp32
__device__ float  g_buf2[(size_t)2*VOL_FULL*16];   // conv2 raw, NHWC fp32
__device__ float  g_buf3[2*32*VOL_HALF];           // conv3 raw, NCHW fp32
__device__ double g_redp[3][64][64];
__device__ float  g_sbt[3][64];
__device__ float  g_gemm[2*N_PATCH*N_T];

__device__ __nv_bfloat16 g_ahi[2*32*VOL_HALF];
__device__ __nv_bfloat16 g_alo[2*32*VOL_HALF];
__device__ __nv_bfloat16 g_whi[(size_t)N_T*PDIM];
__device__ __nv_bfloat16 g_wlo[(size_t)N_T*PDIM];
__device__ __nv_bfloat16 g_w2h[6912];
__device__ __nv_bfloat16 g_w2l[6912];
__device__ __nv_bfloat16 g_w3h[13824];
__device__ __nv_bfloat16 g_w3l[13824];

__device__ __forceinline__ u64 pk2(float x, float y) {
    u64 r; asm("mov.b64 %0,{%1,%2};" : "=l"(r) : "f"(x), "f"(y)); return r;
}
__device__ __forceinline__ float2 upk(u64 v) {
    float2 r; asm("mov.b64 {%0,%1},%2;" : "=f"(r.x), "=f"(r.y) : "l"(v)); return r;
}
__device__ __forceinline__ void fma2(u64& d, u64 a, u64 b) {
    asm("fma.rn.f32x2 %0,%1,%2,%0;" : "+l"(d) : "l"(a), "l"(b));
}
__device__ __forceinline__ uint32_t smem_u32(const void* p) {
    uint32_t a;
    asm("{ .reg .u64 t; cvta.to.shared.u64 t, %1; cvt.u32.u64 %0, t; }" : "=r"(a) : "l"(p));
    return a;
}
__device__ __forceinline__ void ldsm4(uint32_t* r, uint32_t addr) {
    asm volatile("ldmatrix.sync.aligned.m8n8.x4.shared.b16 {%0,%1,%2,%3}, [%4];"
        : "=r"(r[0]), "=r"(r[1]), "=r"(r[2]), "=r"(r[3]) : "r"(addr));
}
__device__ __forceinline__ void mma_bf16(float* d, const uint32_t* a,
                                         uint32_t b0, uint32_t b1) {
    asm volatile("mma.sync.aligned.m16n8k16.row.col.f32.bf16.bf16.f32 "
        "{%0,%1,%2,%3}, {%4,%5,%6,%7}, {%8,%9}, {%0,%1,%2,%3};"
        : "+f"(d[0]), "+f"(d[1]), "+f"(d[2]), "+f"(d[3])
        : "r"(a[0]), "r"(a[1]), "r"(a[2]), "r"(a[3]), "r"(b0), "r"(b1));
}

// ---------------------------------------------------------------------------
__global__ void k_zero() {
    int i = blockIdx.x * blockDim.x + threadIdx.x;
    if (i < 2*N_PATCH*N_T) g_gemm[i] = 0.f;
    if (i < 3*64*64) ((double*)g_redp)[i] = 0.0;
}

// ---------------------------------------------------------------------------
// conv1: 1->16, FFMA2, TWO y-rows; NHWC fp32 out via smem staging; stats 0.
__global__ void __launch_bounds__(128) k_conv1(const float* __restrict__ in,
                                               const float* __restrict__ w)
{
    __shared__ __align__(16) float sm_in[13*128];
    __shared__ float sm_w[27*16];
    __shared__ __align__(16) float sm_out[2*16*132];
    const int y0 = 2*blockIdx.x, z = blockIdx.y, b = blockIdx.z;
    const int t = threadIdx.x, l = t & 31, g = t >> 5;

    for (int i = t; i < 27*16; i += 128) {
        int co = i & 15, k = i >> 4;
        sm_w[i] = w[co*27 + k];
    }
    {
        const float* inc = in + (size_t)b * VOL_FULL;
#pragma unroll
        for (int j = 0; j < 13; j++) {
            int i = t + 128*j;
            float v = 0.f;
            if (i < 1584) {
                int r = i / 132, idx = i - 132*r;
                int gz = z - 1 + (r >> 2), gy = y0 - 1 + (r & 3), gx = idx - 1;
                if ((unsigned)gz < 128u && (unsigned)gy < 128u && (unsigned)gx < 128u)
                    v = inc[(gz*128 + gy)*128 + gx];
            }
            if (i < 13*128) sm_in[i] = v;
        }
    }
    __syncthreads();

    u64 acc[2][2][4];
#pragma unroll
    for (int yr = 0; yr < 2; yr++)
#pragma unroll
        for (int j2 = 0; j2 < 2; j2++)
#pragma unroll
            for (int xx = 0; xx < 4; xx++) acc[yr][j2][xx] = 0ULL;

#pragma unroll
    for (int r = 0; r < 12; r++) {
        float4 A = *(const float4*)(sm_in + r*132 + 4*l);
        float4 B = *(const float4*)(sm_in + r*132 + 4*l + 4);
        float a[7] = {A.x, A.y, A.z, A.w, B.x, B.y, B.z};
        u64 pv[7];
#pragma unroll
        for (int j = 0; j < 7; j++) pv[j] = pk2(a[j], a[j]);
        const int dz = r >> 2, m = r & 3;
#pragma unroll
        for (int yr = 0; yr < 2; yr++) {
            const int dyy = m - yr;
            if (dyy < 0 || dyy > 2) continue;
            const int kb = dz*9 + dyy*3;
#pragma unroll
            for (int dx = 0; dx < 3; dx++) {
                u64 w0 = *(const u64*)(sm_w + (kb+dx)*16 + g*4);
                u64 w1 = *(const u64*)(sm_w + (kb+dx)*16 + g*4 + 2);
#pragma unroll
                for (int xx = 0; xx < 4; xx++) {
                    fma2(acc[yr][0][xx], pv[dx+xx], w0);
                    fma2(acc[yr][1][xx], pv[dx+xx], w1);
                }
            }
        }
    }

    float2 v[2][2][4];
#pragma unroll
    for (int yr = 0; yr < 2; yr++)
#pragma unroll
        for (int j2 = 0; j2 < 2; j2++)
#pragma unroll
            for (int xx = 0; xx < 4; xx++) v[yr][j2][xx] = upk(acc[yr][j2][xx]);

#pragma unroll
    for (int yr = 0; yr < 2; yr++)
#pragma unroll
        for (int j2 = 0; j2 < 2; j2++) {
            int co = g*4 + 2*j2;
#pragma unroll
            for (int xx = 0; xx < 4; xx++) {
                sm_out[(yr*16 + co)*132 + 4*l + xx]   = v[yr][j2][xx].x;
                sm_out[(yr*16 + co+1)*132 + 4*l + xx] = v[yr][j2][xx].y;
            }
        }
    __syncthreads();

#pragma unroll
    for (int p = 0; p < 2; p++) {
        int vox = t + 128*p;
        int yr = vox >> 7, x = vox & 127;
        float o[16];
#pragma unroll
        for (int c = 0; c < 16; c++) o[c] = sm_out[(yr*16 + c)*132 + x];
        float* dst = g_buf1 + ((size_t)b*VOL_FULL + ((size_t)z*128 + y0 + yr)*128 + x)*16;
        *(float4*)(dst)      = make_float4(o[0], o[1], o[2], o[3]);
        *(float4*)(dst + 4)  = make_float4(o[4], o[5], o[6], o[7]);
        *(float4*)(dst + 8)  = make_float4(o[8], o[9], o[10], o[11]);
        *(float4*)(dst + 12) = make_float4(o[12], o[13], o[14], o[15]);
    }

#pragma unroll
    for (int c = 0; c < 4; c++) {
        float s = 0.f, q = 0.f;
#pragma unroll
        for (int yr = 0; yr < 2; yr++)
#pragma unroll
            for (int xx = 0; xx < 4; xx++) {
                float val = (c & 1) ? v[yr][c>>1][xx].y : v[yr][c>>1][xx].x;
                s += val; q = fmaf(val, val, q);
            }
#pragma unroll
        for (int o = 16; o; o >>= 1) {
            s += __shfl_down_sync(0xffffffffu, s, o);
            q += __shfl_down_sync(0xffffffffu, q, o);
        }
        if (l == 0) {
            atomicAdd(&g_redp[0][z & 63][g*4 + c],      (double)s);
            atomicAdd(&g_redp[0][z & 63][32 + g*4 + c], (double)q);
        }
    }
}

// ---------------------------------------------------------------------------
// merged conv2 + conv3 weight decomposition (one launch)
__global__ void k_decompW23(const float* __restrict__ w2,
                            const float* __restrict__ w3) {
    for (int i = threadIdx.x; i < 6912; i += 256) {
        int ci = i & 15, co = (i >> 4) & 15, tap = i >> 8;
        float v = w2[(co*16 + ci)*27 + tap];
        __nv_bfloat16 h = __float2bfloat16(v);
        g_w2h[i] = h;
        g_w2l[i] = __float2bfloat16(v - __bfloat162float(h));
    }
    for (int i = threadIdx.x; i < 13824; i += 256) {
        int ci = i & 15, co = (i >> 4) & 31, tap = i >> 9;
        float v = w3[(co*16 + ci)*27 + tap];
        __nv_bfloat16 h = __float2bfloat16(v);
        g_w3h[i] = h;
        g_w3l[i] = __float2bfloat16(v - __bfloat162float(h));
    }
}

// ---------------------------------------------------------------------------
// conv2 ring2 (R11): 4 y-rows, 16 z, 512 thr / 16 warps, warp = m32.
#define R2_SLOT   24960
#define R2_ALO    99840
#define R2_BHI    199680
#define R2_BLO    213504
#define R2_SB     227328
#define R2_SMEM   227584

__global__ void __launch_bounds__(512, 1) k_conv2_ring2()
{
    extern __shared__ __align__(16) char smem[];
    const uint32_t sb = smem_u32(smem);
    float* smSB = (float*)(smem + R2_SB);
    const int yq = blockIdx.x, zs = blockIdx.y, b = blockIdx.z;
    const int y0 = 4*yq, z0 = 16*zs;
    const int tid = threadIdx.x, wid = tid >> 5, lane = tid & 31;

    if (tid < 64) smSB[tid] = g_sbt[0][tid];

    for (int i = tid; i < 864; i += 512) {
        int row = i >> 1, hf = i & 1;
        uint4 vh = *(const uint4*)(g_w2h + row*16 + hf*8);
        uint4 vl = *(const uint4*)(g_w2l + row*16 + hf*8);
        uint32_t off = (uint32_t)row*32 + (((uint32_t)hf ^ ((uint32_t)(row>>2)&1)) << 4);
        *(uint4*)(smem + R2_BHI + off) = vh;
        *(uint4*)(smem + R2_BLO + off) = vl;
    }
    __syncthreads();

    auto fillplane = [&](int p) {
        int slot = (p & 3);
        char* ah = smem + slot*R2_SLOT;
        char* al = smem + R2_ALO + slot*R2_SLOT;
        for (int i = tid; i < 780; i += 512) {
            int dyr = i / 130, xs = i - dyr*130;
            int gx = xs - 1, gy = y0 - 1 + dyr;
            __align__(16) __nv_bfloat16 h[16], lo[16];
            if ((unsigned)p < 128u && (unsigned)gy < 128u && (unsigned)gx < 128u) {
                const float4* src = (const float4*)(g_buf1
                    + ((size_t)b*VOL_FULL + ((size_t)p*128 + gy)*128 + gx)*16);
                float4 q0 = src[0], q1 = src[1], q2 = src[2], q3 = src[3];
                float f[16] = {q0.x,q0.y,q0.z,q0.w, q1.x,q1.y,q1.z,q1.w,
                               q2.x,q2.y,q2.z,q2.w, q3.x,q3.y,q3.z,q3.w};
#pragma unroll
                for (int c = 0; c < 16; c++) {
                    float vv = fmaxf(fmaf(f[c], smSB[c], smSB[32 + c]), 0.f);
                    h[c] = __float2bfloat16(vv);
                    lo[c] = __float2bfloat16(vv - __bfloat162float(h[c]));
                }
            } else {
#pragma unroll
                for (int c = 0; c < 16; c++) { h[c] = __float2bfloat16(0.f); lo[c] = h[c]; }
            }
            uint32_t pb = (uint32_t)((i >> 2) & 1);
            uint32_t o0 = (uint32_t)i*32 + (pb << 4);
            uint32_t o1 = (uint32_t)i*32 + ((1u ^ pb) << 4);
            *(uint4*)(ah + o0) = *(uint4*)h;
            *(uint4*)(ah + o1) = *(uint4*)(h + 8);
            *(uint4*)(al + o0) = *(uint4*)lo;
            *(uint4*)(al + o1) = *(uint4*)(lo + 8);
        }
    };

    fillplane(z0 - 1);
    fillplane(z0);

    const int yr = wid >> 2, xt = wid & 3;
    const int mrow = lane & 15;
    const uint32_t ahalf = (uint32_t)(lane >> 4);
    const int browl = ((lane >> 4) << 3) + (lane & 7);
    const uint32_t bhalf = (uint32_t)((lane >> 3) & 1);

    float sacc[4] = {0.f,0.f,0.f,0.f}, qacc[4] = {0.f,0.f,0.f,0.f};

    for (int z = z0; z < z0 + 16; z++) {
        fillplane(z + 1);
        __syncthreads();

        uint32_t sb_a[3];
#pragma unroll
        for (int dz = 0; dz < 3; dz++)
            sb_a[dz] = (uint32_t)(((z - 1 + dz) & 3) * R2_SLOT);

        float d[2][2][4];
#pragma unroll
        for (int mt = 0; mt < 2; mt++)
#pragma unroll
            for (int nt = 0; nt < 2; nt++)
#pragma unroll
                for (int i = 0; i < 4; i++) d[mt][nt][i] = 0.f;

#pragma unroll
        for (int tap = 0; tap < 27; tap++) {
            const int zy = tap / 3, dx = tap % 3;
            const int dz = zy / 3, dy = zy % 3;
            const int rbase = (yr + dy)*130 + 32*xt + dx + mrow;

            uint32_t ah0[4], al0[4], ah1[4], al1[4];
            {
                int r = rbase;
                uint32_t aoff = sb_a[dz] + (uint32_t)r*32
                              + ((ahalf ^ ((uint32_t)(r >> 2) & 1)) << 4);
                ldsm4(ah0, sb + aoff);
                ldsm4(al0, sb + R2_ALO + aoff);
            }
            {
                int r = rbase + 16;
                uint32_t aoff = sb_a[dz] + (uint32_t)r*32
                              + ((ahalf ^ ((uint32_t)(r >> 2) & 1)) << 4);
                ldsm4(ah1, sb + aoff);
                ldsm4(al1, sb + R2_ALO + aoff);
            }

            int br = tap*16 + browl;
            uint32_t boff = (uint32_t)br*32
                          + ((bhalf ^ ((uint32_t)(br >> 2) & 1)) << 4);
            uint32_t bh4[4], bl4[4];
            ldsm4(bh4, sb + R2_BHI + boff);
            ldsm4(bl4, sb + R2_BLO + boff);

            mma_bf16(d[0][0], ah0, bh4[0], bh4[1]);
            mma_bf16(d[0][1], ah0, bh4[2], bh4[3]);
            mma_bf16(d[0][0], ah0, bl4[0], bl4[1]);
            mma_bf16(d[0][1], ah0, bl4[2], bl4[3]);
            mma_bf16(d[0][0], al0, bh4[0], bh4[1]);
            mma_bf16(d[0][1], al0, bh4[2], bh4[3]);

            mma_bf16(d[1][0], ah1, bh4[0], bh4[1]);
            mma_bf16(d[1][1], ah1, bh4[2], bh4[3]);
            mma_bf16(d[1][0], ah1, bl4[0], bl4[1]);
            mma_bf16(d[1][1], ah1, bl4[2], bl4[3]);
            mma_bf16(d[1][0], al1, bh4[0], bh4[1]);
            mma_bf16(d[1][1], al1, bh4[2], bh4[3]);
        }

#pragma unroll
        for (int mt = 0; mt < 2; mt++) {
            int x = 32*xt + 16*mt + (lane >> 2);
            size_t vbase = ((size_t)b*VOL_FULL + ((size_t)z*128 + y0 + yr)*128 + x)*16;
#pragma unroll
            for (int nt = 0; nt < 2; nt++) {
                int c = 8*nt + 2*(lane & 3);
                *(float2*)(g_buf2 + vbase + c)       = make_float2(d[mt][nt][0], d[mt][nt][1]);
                *(float2*)(g_buf2 + vbase + 128 + c) = make_float2(d[mt][nt][2], d[mt][nt][3]);
                sacc[2*nt]   += d[mt][nt][0] + d[mt][nt][2];
                sacc[2*nt+1] += d[mt][nt][1] + d[mt][nt][3];
                qacc[2*nt]   += d[mt][nt][0]*d[mt][nt][0] + d[mt][nt][2]*d[mt][nt][2];
                qacc[2*nt+1] += d[mt][nt][1]*d[mt][nt][1] + d[mt][nt][3]*d[mt][nt][3];
            }
        }
    }

    __syncthreads();
    float* smS = (float*)smem;
    if (tid < 32) smS[tid] = 0.f;
    __syncthreads();
#pragma unroll
    for (int k = 0; k < 4; k++) {
        int c = 8*(k >> 1) + 2*(lane & 3) + (k & 1);
        atomicAdd(&smS[c], sacc[k]);
        atomicAdd(&smS[16 + c], qacc[k]);
    }
    __syncthreads();
    if (tid < 16) {
        int slot = (yq*8 + zs) & 63;
        atomicAdd(&g_redp[1][slot][tid],      (double)smS[tid]);
        atomicAdd(&g_redp[1][slot][32 + tid], (double)smS[16 + tid]);
    }
}

// ---------------------------------------------------------------------------
// conv3 ring (R11): stride-2 16->32 HMMA bf16x3.
#define C3_SLOT 20800
#define C3_ALO  83200
#define C3_BHI  166400
#define C3_BLO  194048
#define C3_SB   221696
#define C3_SMEM 221952

__global__ void __launch_bounds__(256, 1) k_conv3_ring()
{
    extern __shared__ __align__(16) char smem[];
    const uint32_t sb = smem_u32(smem);
    float* smSB = (float*)(smem + C3_SB);
    const int yq = blockIdx.x, zs = blockIdx.y, b = blockIdx.z;
    const int y0 = 2*yq, z0 = 16*zs;
    const int tid = threadIdx.x, wid = tid >> 5, lane = tid & 31;

    if (tid < 64) smSB[tid] = g_sbt[1][tid];

    for (int i = tid; i < 1728; i += 256) {
        int row = i >> 1, hf = i & 1;
        uint4 vh = *(const uint4*)(g_w3h + row*16 + hf*8);
        uint4 vl = *(const uint4*)(g_w3l + row*16 + hf*8);
        uint32_t off = (uint32_t)row*32 + (((uint32_t)hf ^ ((uint32_t)(row>>2)&1)) << 4);
        *(uint4*)(smem + C3_BHI + off) = vh;
        *(uint4*)(smem + C3_BLO + off) = vl;
    }
    __syncthreads();

    auto fillplane = [&](int p) {
        int slot = (p & 3);
        char* ah = smem + slot*C3_SLOT;
        char* al = smem + C3_ALO + slot*C3_SLOT;
        for (int i = tid; i < 650; i += 256) {
            int dyr = i / 130, xs = i - dyr*130;
            int gx = xs - 1, gy = 2*y0 - 1 + dyr;
            __align__(16) __nv_bfloat16 h[16], lo[16];
            if ((unsigned)p < 128u && (unsigned)gy < 128u && (unsigned)gx < 128u) {
                const float4* src = (const float4*)(g_buf2
                    + ((size_t)b*VOL_FULL + ((size_t)p*128 + gy)*128 + gx)*16);
                float4 q0 = src[0], q1 = src[1], q2 = src[2], q3 = src[3];
                float f[16] = {q0.x,q0.y,q0.z,q0.w, q1.x,q1.y,q1.z,q1.w,
                               q2.x,q2.y,q2.z,q2.w, q3.x,q3.y,q3.z,q3.w};
#pragma unroll
                for (int c = 0; c < 16; c++) {
                    float vv = fmaxf(fmaf(f[c], smSB[c], smSB[32 + c]), 0.f);
                    h[c] = __float2bfloat16(vv);
                    lo[c] = __float2bfloat16(vv - __bfloat162float(h[c]));
                }
            } else {
#pragma unroll
                for (int c = 0; c < 16; c++) { h[c] = __float2bfloat16(0.f); lo[c] = h[c]; }
            }
            uint32_t pb = (uint32_t)((i >> 2) & 1);
            uint32_t o0 = (uint32_t)i*32 + (pb << 4);
            uint32_t o1 = (uint32_t)i*32 + ((1u ^ pb) << 4);
            *(uint4*)(ah + o0) = *(uint4*)h;
            *(uint4*)(ah + o1) = *(uint4*)(h + 8);
            *(uint4*)(al + o0) = *(uint4*)lo;
            *(uint4*)(al + o1) = *(uint4*)(lo + 8);
        }
    };

    fillplane(2*z0 - 1);

    const int yrow = wid >> 2, xt = wid & 3;
    const int mrow = lane & 15;
    const uint32_t ahalf = (uint32_t)(lane >> 4);
    const int browl = ((lane >> 4) << 3) + (lane & 7);
    const uint32_t bhalf = (uint32_t)((lane >> 3) & 1);

    float sacc[8], qacc[8];
#pragma unroll
    for (int k = 0; k < 8; k++) { sacc[k] = 0.f; qacc[k] = 0.f; }

    for (int z = z0; z < z0 + 16; z++) {
        __syncthreads();
        fillplane(2*z);
        fillplane(2*z + 1);
        __syncthreads();

        uint32_t sb_a[3];
#pragma unroll
        for (int dz = 0; dz < 3; dz++)
            sb_a[dz] = (uint32_t)(((2*z - 1 + dz) & 3) * C3_SLOT);

        float d[4][4];
#pragma unroll
        for (int nt = 0; nt < 4; nt++)
#pragma unroll
            for (int i = 0; i < 4; i++) d[nt][i] = 0.f;

#pragma unroll
        for (int tap = 0; tap < 27; tap++) {
            const int zy = tap / 3, dx = tap % 3;
            const int dz = zy / 3, dy = zy % 3;
            int r = (2*yrow + dy)*130 + 2*(16*xt + mrow) + dx;
            uint32_t aoff = sb_a[dz] + (uint32_t)r*32
                          + ((ahalf ^ ((uint32_t)(r >> 2) & 1)) << 4);
            uint32_t ah4[4], al4[4];
            ldsm4(ah4, sb + aoff);
            ldsm4(al4, sb + C3_ALO + aoff);

#pragma unroll
            for (int gq = 0; gq < 2; gq++) {
                int br = tap*32 + gq*16 + browl;
                uint32_t boff = (uint32_t)br*32
                              + ((bhalf ^ ((uint32_t)(br >> 2) & 1)) << 4);
                uint32_t bh4[4], bl4[4];
                ldsm4(bh4, sb + C3_BHI + boff);
                ldsm4(bl4, sb + C3_BLO + boff);

                mma_bf16(d[2*gq],   ah4, bh4[0], bh4[1]);
                mma_bf16(d[2*gq+1], ah4, bh4[2], bh4[3]);
                mma_bf16(d[2*gq],   ah4, bl4[0], bl4[1]);
                mma_bf16(d[2*gq+1], ah4, bl4[2], bl4[3]);
                mma_bf16(d[2*gq],   al4, bh4[0], bh4[1]);
                mma_bf16(d[2*gq+1], al4, bh4[2], bh4[3]);
            }
        }

        const int y = y0 + yrow;
        const int xA = 16*xt + (lane >> 2);
#pragma unroll
        for (int nt = 0; nt < 4; nt++) {
            int c = 8*nt + 2*(lane & 3);
            size_t base0 = (size_t)(b*32 + c)*VOL_HALF + (size_t)z*4096 + y*64 + xA;
            g_buf3[base0]                = d[nt][0];
            g_buf3[base0 + VOL_HALF]     = d[nt][1];
            g_buf3[base0 + 8]            = d[nt][2];
            g_buf3[base0 + VOL_HALF + 8] = d[nt][3];
            sacc[2*nt]   += d[nt][0] + d[nt][2];
            sacc[2*nt+1] += d[nt][1] + d[nt][3];
            qacc[2*nt]   += d[nt][0]*d[nt][0] + d[nt][2]*d[nt][2];
            qacc[2*nt+1] += d[nt][1]*d[nt][1] + d[nt][3]*d[nt][3];
        }
    }

    __syncthreads();
    float* smS = (float*)smem;
    if (tid < 64) smS[tid] = 0.f;
    __syncthreads();
#pragma unroll
    for (int k = 0; k < 8; k++) {
        int c = 8*(k >> 1) + 2*(lane & 3) + (k & 1);
        atomicAdd(&smS[c], sacc[k]);
        atomicAdd(&smS[32 + c], qacc[k]);
    }
    __syncthreads();
    if (tid < 32) {
        int slot = (yq*4 + zs) & 63;
        atomicAdd(&g_redp[2][slot][tid],      (double)smS[tid]);
        atomicAdd(&g_redp[2][slot][32 + tid], (double)smS[32 + tid]);
    }
}

// ---------------------------------------------------------------------------
__global__ void __launch_bounds__(256) k_finalize(int stage, int C, float invN,
                                                  const float* __restrict__ g,
                                                  const float* __restrict__ b)
{
    __shared__ double sS[8][32], sQ[8][32];
    const int tid = threadIdx.x;
    const int c = tid & 31, part = tid >> 5;
    double s = 0.0, q = 0.0;
    for (int i = part; i < 64; i += 8) {
        s += g_redp[stage][i][c];
        q += g_redp[stage][i][32 + c];
    }
    sS[part][c] = s; sQ[part][c] = q;
    __syncthreads();
    if (tid < 32 && tid < C) {
        double S = 0.0, Q = 0.0;
#pragma unroll
        for (int p = 0; p < 8; p++) { S += sS[p][tid]; Q += sQ[p][tid]; }
        double mean = S * (double)invN;
        double var  = Q * (double)invN - mean*mean;
        float sc = g[tid] * rsqrtf((float)var + 1e-5f);
        g_sbt[stage][tid]      = sc;
        g_sbt[stage][32 + tid] = b[tid] - (float)mean * sc;
    }
}

// ---------------------------------------------------------------------------
__global__ void __launch_bounds__(256) k_decompW(const float* __restrict__ tok_w,
                                                 const float* __restrict__ aux_w)
{
    size_t gid = (size_t)blockIdx.x*256 + threadIdx.x;
    size_t e = gid*8;
    if (e >= (size_t)N_T*PDIM) return;
    int t = (int)(e >> 17);
    int k = (int)(e & (PDIM-1));
    const float* src = (t < 128) ? tok_w + ((size_t)t << 17) + k
                                 : aux_w + ((size_t)(t-128) << 17) + k;
    float4 a = ((const float4*)src)[0];
    float4 c = ((const float4*)src)[1];
    float v[8] = {a.x,a.y,a.z,a.w, c.x,c.y,c.z,c.w};
    __align__(16) __nv_bfloat16 h[8];
    __align__(16) __nv_bfloat16 l[8];
#pragma unroll
    for (int j = 0; j < 8; j++) {
        h[j] = __float2bfloat16(v[j]);
        l[j] = __float2bfloat16(v[j] - __bfloat162float(h[j]));
    }
    *(uint4*)(g_whi + e) = *(uint4*)h;
    *(uint4*)(g_wlo + e) = *(uint4*)l;
}

__global__ void __launch_bounds__(256) k_decompA()
{
    size_t gid = (size_t)blockIdx.x*256 + threadIdx.x;
    size_t e = gid*8;
    if (e >= (size_t)2*32*VOL_HALF) return;
    int ci = (int)((e >> 18) & 31);
    float s_ = g_sbt[2][ci], b_ = g_sbt[2][32 + ci];
    float4 a = *(const float4*)(g_buf3 + e);
    float4 c = *(const float4*)(g_buf3 + e + 4);
    float v[8] = {a.x,a.y,a.z,a.w, c.x,c.y,c.z,c.w};
    __align__(16) __nv_bfloat16 h[8];
    __align__(16) __nv_bfloat16 l[8];
#pragma unroll
    for (int j = 0; j < 8; j++) {
        float x = fmaxf(fmaf(v[j], s_, b_), 0.f);
        h[j] = __float2bfloat16(x);
        l[j] = __float2bfloat16(x - __bfloat162float(h[j]));
    }
    *(uint4*)(g_ahi + e) = *(uint4*)h;
    *(uint4*)(g_alo + e) = *(uint4*)l;
}

// ---------------------------------------------------------------------------
// HMMA bf16x3 patch GEMM, K-split x2, warp tile m32 x n80 (B-ldsm halved).
#define A_HI 0
#define A_LO 18432
#define B_HI 36864
#define B_LO 59904
#define GEMM_SMEM 82944

__global__ void __launch_bounds__(256, 2) k_gemm_tc()
{
    extern __shared__ __align__(16) char smem[];
    const uint32_t sb = smem_u32(smem);
    const int tile = blockIdx.x;
    const int ci = blockIdx.y >> 1, kh = blockIdx.y & 1;
    const int tid = threadIdx.x, w = tid >> 5, lane = tid & 31;
    const int mg = w & 3, ng = w >> 2;    // warp tile: m32 (rows 32mg), n80 (j in [5ng,5ng+5))

    int m = tile*128 + tid;
    bool valid = (tid < 128) && (m < 686);
    int b = 0, pz = 0, py = 0, px = 0;
    if (valid) {
        b = (m >= 343) ? 1 : 0;
        int n = m - 343*b;
        pz = n / 49; int r2 = n - 49*pz;
        py = r2 / 7; px = r2 - 7*py;
    }
    const size_t chan = (size_t)(b*32 + ci)*64;

    // A lane bases for the warp's two m16 sub-tiles
    uint32_t aHiB[2], aLoB[2];
#pragma unroll
    for (int mt = 0; mt < 2; mt++) {
        uint32_t off = (uint32_t)((32*mg + 16*mt + (lane & 15))*144 + ((lane >> 4)*8)*2);
        aHiB[mt] = sb + A_HI + off;
        aLoB[mt] = sb + A_LO + off;
    }
    const uint32_t bOff = (uint32_t)((((lane >> 4) << 3) + (lane & 7))*144
                                     + (((lane >> 3) & 1)*8)*2);
    const uint32_t bHiB = sb + B_HI + bOff;
    const uint32_t bLoB = sb + B_LO + bOff;

    float d[2][10][4];
#pragma unroll
    for (int mt = 0; mt < 2; mt++)
#pragma unroll
        for (int nt = 0; nt < 10; nt++)
#pragma unroll
            for (int i = 0; i < 4; i++) d[mt][nt][i] = 0.f;

    const size_t kcol = (size_t)ci*4096;

    for (int cc = 0; cc < 32; cc++) {
        const int chunk = kh*32 + cc;
        __syncthreads();

        if (tid < 128) {
            const int dz = chunk >> 2, dy0 = (chunk & 3) << 2;
#pragma unroll
            for (int j = 0; j < 4; j++) {
                uint4 h0 = make_uint4(0,0,0,0), h1 = h0, l0 = h0, l1 = h0;
                if (valid) {
                    size_t idx = (chan + 8*pz + dz)*4096
                               + (size_t)(8*py + dy0 + j)*64 + 8*px;
                    h0 = *(const uint4*)(g_ahi + idx);
                    h1 = *(const uint4*)(g_ahi + idx + 8);
                    l0 = *(const uint4*)(g_alo + idx);
                    l1 = *(const uint4*)(g_alo + idx + 8);
                }
                int dst = tid*144 + j*32;
                *(uint4*)(smem + A_HI + dst)      = h0;
                *(uint4*)(smem + A_HI + dst + 16) = h1;
                *(uint4*)(smem + A_LO + dst)      = l0;
                *(uint4*)(smem + A_LO + dst + 16) = l1;
            }
        }
        {
            const size_t kb = kcol + (size_t)chunk*64;
#pragma unroll
            for (int i = tid; i < 1280; i += 256) {
                int n = i >> 3, seg = i & 7;
                size_t so = (size_t)n*PDIM + kb + seg*8;
                int dst = n*144 + seg*16;
                *(uint4*)(smem + B_HI + dst) = *(const uint4*)(g_whi + so);
                *(uint4*)(smem + B_LO + dst) = *(const uint4*)(g_wlo + so);
            }
        }
        __syncthreads();

#pragma unroll
        for (int ks = 0; ks < 4; ks++) {
            uint32_t ah[2][4], al[2][4];
#pragma unroll
            for (int mt = 0; mt < 2; mt++) {
                ldsm4(ah[mt], aHiB[mt] + ks*32);
                ldsm4(al[mt], aLoB[mt] + ks*32);
            }
#pragma unroll
            for (int jg = 0; jg < 5; jg++) {
                const int j = 5*ng + jg;
                uint32_t bh[4], bl[4];
                ldsm4(bh, bHiB + j*2304 + ks*32);
                ldsm4(bl, bLoB + j*2304 + ks*32);
#pragma unroll
                for (int mt = 0; mt < 2; mt++) {
                    mma_bf16(d[mt][2*jg],   ah[mt], bh[0], bh[1]);
                    mma_bf16(d[mt][2*jg+1], ah[mt], bh[2], bh[3]);
                    mma_bf16(d[mt][2*jg],   ah[mt], bl[0], bl[1]);
                    mma_bf16(d[mt][2*jg+1], ah[mt], bl[2], bl[3]);
                    mma_bf16(d[mt][2*jg],   al[mt], bh[0], bh[1]);
                    mma_bf16(d[mt][2*jg+1], al[mt], bh[2], bh[3]);
                }
            }
        }
    }

    const int qc = 2*(lane & 3);
#pragma unroll
    for (int mt = 0; mt < 2; mt++) {
        const int mr = tile*128 + 32*mg + 16*mt + (lane >> 2);
#pragma unroll
        for (int nt = 0; nt < 10; nt++) {
            int col = 8*(10*ng + nt) + qc;
            if (mr < 686) {
                atomicAdd(&g_gemm[mr*N_T + col],     d[mt][nt][0]);
                atomicAdd(&g_gemm[mr*N_T + col + 1], d[mt][nt][1]);
            }
            if (mr + 8 < 686) {
                atomicAdd(&g_gemm[(mr+8)*N_T + col],     d[mt][nt][2]);
                atomicAdd(&g_gemm[(mr+8)*N_T + col + 1], d[mt][nt][3]);
            }
        }
    }
}

// ---------------------------------------------------------------------------
__global__ void k_final(const float* __restrict__ tok_b,
                        const float* __restrict__ aux_b,
                        const float* __restrict__ ln_g,
                        const float* __restrict__ ln_b,
                        float* __restrict__ out)
{
    const int bn = blockIdx.x;
    const int n = bn % N_PATCH;
    const int t = threadIdx.x;

    float v = g_gemm[bn*N_T + t] + tok_b[t];
    float s = v, q = v*v;
#pragma unroll
    for (int o = 16; o; o >>= 1) {
        s += __shfl_down_sync(0xffffffffu, s, o);
        q += __shfl_down_sync(0xffffffffu, q, o);
    }
    __shared__ float ss[4], qq[4];
    int wp = t >> 5, ln = t & 31;
    if (ln == 0) { ss[wp] = s; qq[wp] = q; }
    __syncthreads();
    float S1 = ss[0] + ss[1] + ss[2] + ss[3];
    float S2 = qq[0] + qq[1] + qq[2] + qq[3];
    float mean = S1 * (1.f/128.f);
    float var  = S2 * (1.f/128.f) - mean*mean;
    float r = rsqrtf(var + 1e-5f);

    out[bn*128 + t] = (v - mean) * r * ln_g[t] + ln_b[t];

    if (t < 32)
        out[87808 + bn*32 + t] = g_gemm[bn*N_T + 128 + t] + aux_b[t];

    if (t < 3) {
        int pz = n / 49, py = (n / 7) % 7, px = n % 7;
        float c;
        if      (t == 0) c = ((float)pz * 8.f + 7.5f) * (1.f/63.f);
        else if (t == 1) c = ((float)py * 8.f + 7.5f) * (1.f/63.f);
        else             c = ((float)px * 8.f + 7.5f) * (1.f/63.f);
        out[109760 + bn*3 + t] = c;
    }
}

// ---------------------------------------------------------------------------
extern "C" void kernel_launch(void* const* d_in, const int* in_sizes, int n_in,
                              void* d_out, int out_size) {
    const float* x     = (const float*)d_in[0];
    const float* c1w   = (const float*)d_in[1];
    const float* bn1g  = (const float*)d_in[2];
    const float* bn1b  = (const float*)d_in[3];
    const float* c2w   = (const float*)d_in[4];
    const float* bn2g  = (const float*)d_in[5];
    const float* bn2b  = (const float*)d_in[6];
    const float* c3w   = (const float*)d_in[7];
    const float* bn3g  = (const float*)d_in[8];
    const float* bn3b  = (const float*)d_in[9];
    const float* tokw  = (const float*)d_in[10];
    const float* tokb  = (const float*)d_in[11];
    const float* auxw  = (const float*)d_in[12];
    const float* auxb  = (const float*)d_in[13];
    const float* lng   = (const float*)d_in[14];
    const float* lnb   = (const float*)d_in[15];
    float* out = (float*)d_out;

    cudaFuncSetAttribute(k_gemm_tc, cudaFuncAttributeMaxDynamicSharedMemorySize,
                         GEMM_SMEM);
    cudaFuncSetAttribute(k_conv2_ring2, cudaFuncAttributeMaxDynamicSharedMemorySize,
                         R2_SMEM);
    cudaFuncSetAttribute(k_conv3_ring, cudaFuncAttributeMaxDynamicSharedMemorySize,
                         C3_SMEM);

    k_zero<<<(2*N_PATCH*N_T + 255)/256, 256>>>();

    k_decompW<<<(int)(((size_t)N_T*PDIM/8 + 255)/256), 256>>>(tokw, auxw);
    k_decompW23<<<1, 256>>>(c2w, c3w);

    // conv1 -> g_buf1 NHWC fp32 + stats 0
    k_conv1<<<dim3(64,128,2), 128>>>(x, c1w);
    k_finalize<<<1, 256>>>(0, 16, 1.f/(2.f*VOL_FULL), bn1g, bn1b);

    // conv2 (512-thr m32 HMMA ring) -> g_buf2 NHWC fp32 + stats 1
    k_conv2_ring2<<<dim3(32,8,2), 512, R2_SMEM>>>();
    k_finalize<<<1, 256>>>(1, 16, 1.f/(2.f*VOL_FULL), bn2g, bn2b);

    // conv3 (HMMA stride-2 ring) -> g_buf3 NCHW fp32 + stats 2
    k_conv3_ring<<<dim3(32,4,2), 256, C3_SMEM>>>();
    k_finalize<<<1, 256>>>(2, 32, 1.f/(2.f*VOL_HALF), bn3g, bn3b);

    // decompA (restored: separate pass measured faster than fused fill)
    k_decompA<<<(int)(((size_t)2*32*VOL_HALF/8 + 255)/256), 256>>>();

    // gemm (m32 x n80 warp tile, K-split x2)
    k_gemm_tc<<<dim3(6, 64), 256, GEMM_SMEM>>>();

    k_final<<<686, 128>>>(tokb, auxb, lng, lnb, out);
}

// round 15
// speedup vs baseline: 1.0604x; 1.0009x over previous
#include <cuda_runtime.h>
#include <cuda_bf16.h>
#include <cstdint>

// ---------------------------------------------------------------------------
// InputStem R15: R14 + conv1 weight-quad LDS.128 (108->54 weight L1 ops) +
// k_zero folded into k_decompW. Everything else identical to R14.
// ---------------------------------------------------------------------------

#define VOL_FULL (128*128*128)
#define VOL_HALF (64*64*64)
#define N_PATCH  343
#define N_T      160
#define PDIM     131072

typedef unsigned long long u64;

__device__ float  g_buf1[(size_t)2*VOL_FULL*16];   // conv1 raw, NHWC fp32
__device__ float  g_buf2[(size_t)2*VOL_FULL*16];   // conv2 raw, NHWC fp32
__device__ float  g_buf3[2*32*VOL_HALF];           // conv3 raw, NCHW fp32
__device__ double g_redp[3][64][64];
__device__ float  g_sbt[3][64];
__device__ float  g_gemm[2*N_PATCH*N_T];

__device__ __nv_bfloat16 g_ahi[2*32*VOL_HALF];
__device__ __nv_bfloat16 g_alo[2*32*VOL_HALF];
__device__ __nv_bfloat16 g_whi[(size_t)N_T*PDIM];
__device__ __nv_bfloat16 g_wlo[(size_t)N_T*PDIM];
__device__ __nv_bfloat16 g_w2h[6912];
__device__ __nv_bfloat16 g_w2l[6912];
__device__ __nv_bfloat16 g_w3h[13824];
__device__ __nv_bfloat16 g_w3l[13824];

__device__ __forceinline__ u64 pk2(float x, float y) {
    u64 r; asm("mov.b64 %0,{%1,%2};" : "=l"(r) : "f"(x), "f"(y)); return r;
}
__device__ __forceinline__ float2 upk(u64 v) {
    float2 r; asm("mov.b64 {%0,%1},%2;" : "=f"(r.x), "=f"(r.y) : "l"(v)); return r;
}
__device__ __forceinline__ void fma2(u64& d, u64 a, u64 b) {
    asm("fma.rn.f32x2 %0,%1,%2,%0;" : "+l"(d) : "l"(a), "l"(b));
}
__device__ __forceinline__ uint32_t smem_u32(const void* p) {
    uint32_t a;
    asm("{ .reg .u64 t; cvta.to.shared.u64 t, %1; cvt.u32.u64 %0, t; }" : "=r"(a) : "l"(p));
    return a;
}
__device__ __forceinline__ void ldsm4(uint32_t* r, uint32_t addr) {
    asm volatile("ldmatrix.sync.aligned.m8n8.x4.shared.b16 {%0,%1,%2,%3}, [%4];"
        : "=r"(r[0]), "=r"(r[1]), "=r"(r[2]), "=r"(r[3]) : "r"(addr));
}
__device__ __forceinline__ void mma_bf16(float* d, const uint32_t* a,
                                         uint32_t b0, uint32_t b1) {
    asm volatile("mma.sync.aligned.m16n8k16.row.col.f32.bf16.bf16.f32 "
        "{%0,%1,%2,%3}, {%4,%5,%6,%7}, {%8,%9}, {%0,%1,%2,%3};"
        : "+f"(d[0]), "+f"(d[1]), "+f"(d[2]), "+f"(d[3])
        : "r"(a[0]), "r"(a[1]), "r"(a[2]), "r"(a[3]), "r"(b0), "r"(b1));
}

// ---------------------------------------------------------------------------
// conv1: 1->16, FFMA2, TWO y-rows; NHWC fp32 out via smem staging; stats 0.
// R15: weight quad loaded with ONE LDS.128 (was 2x LDS.64).
__global__ void __launch_bounds__(128) k_conv1(const float* __restrict__ in,
                                               const float* __restrict__ w)
{
    __shared__ __align__(16) float sm_in[13*128];
    __shared__ __align__(16) float sm_w[27*16];
    __shared__ __align__(16) float sm_out[2*16*132];
    const int y0 = 2*blockIdx.x, z = blockIdx.y, b = blockIdx.z;
    const int t = threadIdx.x, l = t & 31, g = t >> 5;

    for (int i = t; i < 27*16; i += 128) {
        int co = i & 15, k = i >> 4;
        sm_w[i] = w[co*27 + k];
    }
    {
        const float* inc = in + (size_t)b * VOL_FULL;
#pragma unroll
        for (int j = 0; j < 13; j++) {
            int i = t + 128*j;
            float v = 0.f;
            if (i < 1584) {
                int r = i / 132, idx = i - 132*r;
                int gz = z - 1 + (r >> 2), gy = y0 - 1 + (r & 3), gx = idx - 1;
                if ((unsigned)gz < 128u && (unsigned)gy < 128u && (unsigned)gx < 128u)
                    v = inc[(gz*128 + gy)*128 + gx];
            }
            if (i < 13*128) sm_in[i] = v;
        }
    }
    __syncthreads();

    u64 acc[2][2][4];
#pragma unroll
    for (int yr = 0; yr < 2; yr++)
#pragma unroll
        for (int j2 = 0; j2 < 2; j2++)
#pragma unroll
            for (int xx = 0; xx < 4; xx++) acc[yr][j2][xx] = 0ULL;

#pragma unroll
    for (int r = 0; r < 12; r++) {
        float4 A = *(const float4*)(sm_in + r*132 + 4*l);
        float4 B = *(const float4*)(sm_in + r*132 + 4*l + 4);
        float a[7] = {A.x, A.y, A.z, A.w, B.x, B.y, B.z};
        u64 pv[7];
#pragma unroll
        for (int j = 0; j < 7; j++) pv[j] = pk2(a[j], a[j]);
        const int dz = r >> 2, m = r & 3;
#pragma unroll
        for (int yr = 0; yr < 2; yr++) {
            const int dyy = m - yr;
            if (dyy < 0 || dyy > 2) continue;
            const int kb = dz*9 + dyy*3;
#pragma unroll
            for (int dx = 0; dx < 3; dx++) {
                ulonglong2 wp = *(const ulonglong2*)(sm_w + (kb+dx)*16 + g*4);
#pragma unroll
                for (int xx = 0; xx < 4; xx++) {
                    fma2(acc[yr][0][xx], pv[dx+xx], wp.x);
                    fma2(acc[yr][1][xx], pv[dx+xx], wp.y);
                }
            }
        }
    }

    float2 v[2][2][4];
#pragma unroll
    for (int yr = 0; yr < 2; yr++)
#pragma unroll
        for (int j2 = 0; j2 < 2; j2++)
#pragma unroll
            for (int xx = 0; xx < 4; xx++) v[yr][j2][xx] = upk(acc[yr][j2][xx]);

#pragma unroll
    for (int yr = 0; yr < 2; yr++)
#pragma unroll
        for (int j2 = 0; j2 < 2; j2++) {
            int co = g*4 + 2*j2;
#pragma unroll
            for (int xx = 0; xx < 4; xx++) {
                sm_out[(yr*16 + co)*132 + 4*l + xx]   = v[yr][j2][xx].x;
                sm_out[(yr*16 + co+1)*132 + 4*l + xx] = v[yr][j2][xx].y;
            }
        }
    __syncthreads();

#pragma unroll
    for (int p = 0; p < 2; p++) {
        int vox = t + 128*p;
        int yr = vox >> 7, x = vox & 127;
        float o[16];
#pragma unroll
        for (int c = 0; c < 16; c++) o[c] = sm_out[(yr*16 + c)*132 + x];
        float* dst = g_buf1 + ((size_t)b*VOL_FULL + ((size_t)z*128 + y0 + yr)*128 + x)*16;
        *(float4*)(dst)      = make_float4(o[0], o[1], o[2], o[3]);
        *(float4*)(dst + 4)  = make_float4(o[4], o[5], o[6], o[7]);
        *(float4*)(dst + 8)  = make_float4(o[8], o[9], o[10], o[11]);
        *(float4*)(dst + 12) = make_float4(o[12], o[13], o[14], o[15]);
    }

#pragma unroll
    for (int c = 0; c < 4; c++) {
        float s = 0.f, q = 0.f;
#pragma unroll
        for (int yr = 0; yr < 2; yr++)
#pragma unroll
            for (int xx = 0; xx < 4; xx++) {
                float val = (c & 1) ? v[yr][c>>1][xx].y : v[yr][c>>1][xx].x;
                s += val; q = fmaf(val, val, q);
            }
#pragma unroll
        for (int o = 16; o; o >>= 1) {
            s += __shfl_down_sync(0xffffffffu, s, o);
            q += __shfl_down_sync(0xffffffffu, q, o);
        }
        if (l == 0) {
            atomicAdd(&g_redp[0][z & 63][g*4 + c],      (double)s);
            atomicAdd(&g_redp[0][z & 63][32 + g*4 + c], (double)q);
        }
    }
}

// ---------------------------------------------------------------------------
// merged conv2 + conv3 weight decomposition (one launch)
__global__ void k_decompW23(const float* __restrict__ w2,
                            const float* __restrict__ w3) {
    for (int i = threadIdx.x; i < 6912; i += 256) {
        int ci = i & 15, co = (i >> 4) & 15, tap = i >> 8;
        float v = w2[(co*16 + ci)*27 + tap];
        __nv_bfloat16 h = __float2bfloat16(v);
        g_w2h[i] = h;
        g_w2l[i] = __float2bfloat16(v - __bfloat162float(h));
    }
    for (int i = threadIdx.x; i < 13824; i += 256) {
        int ci = i & 15, co = (i >> 4) & 31, tap = i >> 9;
        float v = w3[(co*16 + ci)*27 + tap];
        __nv_bfloat16 h = __float2bfloat16(v);
        g_w3h[i] = h;
        g_w3l[i] = __float2bfloat16(v - __bfloat162float(h));
    }
}

// ---------------------------------------------------------------------------
// conv2 ring2 (R11): 4 y-rows, 16 z, 512 thr / 16 warps, warp = m32.
#define R2_SLOT   24960
#define R2_ALO    99840
#define R2_BHI    199680
#define R2_BLO    213504
#define R2_SB     227328
#define R2_SMEM   227584

__global__ void __launch_bounds__(512, 1) k_conv2_ring2()
{
    extern __shared__ __align__(16) char smem[];
    const uint32_t sb = smem_u32(smem);
    float* smSB = (float*)(smem + R2_SB);
    const int yq = blockIdx.x, zs = blockIdx.y, b = blockIdx.z;
    const int y0 = 4*yq, z0 = 16*zs;
    const int tid = threadIdx.x, wid = tid >> 5, lane = tid & 31;

    if (tid < 64) smSB[tid] = g_sbt[0][tid];

    for (int i = tid; i < 864; i += 512) {
        int row = i >> 1, hf = i & 1;
        uint4 vh = *(const uint4*)(g_w2h + row*16 + hf*8);
        uint4 vl = *(const uint4*)(g_w2l + row*16 + hf*8);
        uint32_t off = (uint32_t)row*32 + (((uint32_t)hf ^ ((uint32_t)(row>>2)&1)) << 4);
        *(uint4*)(smem + R2_BHI + off) = vh;
        *(uint4*)(smem + R2_BLO + off) = vl;
    }
    __syncthreads();

    auto fillplane = [&](int p) {
        int slot = (p & 3);
        char* ah = smem + slot*R2_SLOT;
        char* al = smem + R2_ALO + slot*R2_SLOT;
        for (int i = tid; i < 780; i += 512) {
            int dyr = i / 130, xs = i - dyr*130;
            int gx = xs - 1, gy = y0 - 1 + dyr;
            __align__(16) __nv_bfloat16 h[16], lo[16];
            if ((unsigned)p < 128u && (unsigned)gy < 128u && (unsigned)gx < 128u) {
                const float4* src = (const float4*)(g_buf1
                    + ((size_t)b*VOL_FULL + ((size_t)p*128 + gy)*128 + gx)*16);
                float4 q0 = src[0], q1 = src[1], q2 = src[2], q3 = src[3];
                float f[16] = {q0.x,q0.y,q0.z,q0.w, q1.x,q1.y,q1.z,q1.w,
                               q2.x,q2.y,q2.z,q2.w, q3.x,q3.y,q3.z,q3.w};
#pragma unroll
                for (int c = 0; c < 16; c++) {
                    float vv = fmaxf(fmaf(f[c], smSB[c], smSB[32 + c]), 0.f);
                    h[c] = __float2bfloat16(vv);
                    lo[c] = __float2bfloat16(vv - __bfloat162float(h[c]));
                }
            } else {
#pragma unroll
                for (int c = 0; c < 16; c++) { h[c] = __float2bfloat16(0.f); lo[c] = h[c]; }
            }
            uint32_t pb = (uint32_t)((i >> 2) & 1);
            uint32_t o0 = (uint32_t)i*32 + (pb << 4);
            uint32_t o1 = (uint32_t)i*32 + ((1u ^ pb) << 4);
            *(uint4*)(ah + o0) = *(uint4*)h;
            *(uint4*)(ah + o1) = *(uint4*)(h + 8);
            *(uint4*)(al + o0) = *(uint4*)lo;
            *(uint4*)(al + o1) = *(uint4*)(lo + 8);
        }
    };

    fillplane(z0 - 1);
    fillplane(z0);

    const int yr = wid >> 2, xt = wid & 3;
    const int mrow = lane & 15;
    const uint32_t ahalf = (uint32_t)(lane >> 4);
    const int browl = ((lane >> 4) << 3) + (lane & 7);
    const uint32_t bhalf = (uint32_t)((lane >> 3) & 1);

    float sacc[4] = {0.f,0.f,0.f,0.f}, qacc[4] = {0.f,0.f,0.f,0.f};

    for (int z = z0; z < z0 + 16; z++) {
        fillplane(z + 1);
        __syncthreads();

        uint32_t sb_a[3];
#pragma unroll
        for (int dz = 0; dz < 3; dz++)
            sb_a[dz] = (uint32_t)(((z - 1 + dz) & 3) * R2_SLOT);

        float d[2][2][4];
#pragma unroll
        for (int mt = 0; mt < 2; mt++)
#pragma unroll
            for (int nt = 0; nt < 2; nt++)
#pragma unroll
                for (int i = 0; i < 4; i++) d[mt][nt][i] = 0.f;

#pragma unroll
        for (int tap = 0; tap < 27; tap++) {
            const int zy = tap / 3, dx = tap % 3;
            const int dz = zy / 3, dy = zy % 3;
            const int rbase = (yr + dy)*130 + 32*xt + dx + mrow;

            uint32_t ah0[4], al0[4], ah1[4], al1[4];
            {
                int r = rbase;
                uint32_t aoff = sb_a[dz] + (uint32_t)r*32
                              + ((ahalf ^ ((uint32_t)(r >> 2) & 1)) << 4);
                ldsm4(ah0, sb + aoff);
                ldsm4(al0, sb + R2_ALO + aoff);
            }
            {
                int r = rbase + 16;
                uint32_t aoff = sb_a[dz] + (uint32_t)r*32
                              + ((ahalf ^ ((uint32_t)(r >> 2) & 1)) << 4);
                ldsm4(ah1, sb + aoff);
                ldsm4(al1, sb + R2_ALO + aoff);
            }

            int br = tap*16 + browl;
            uint32_t boff = (uint32_t)br*32
                          + ((bhalf ^ ((uint32_t)(br >> 2) & 1)) << 4);
            uint32_t bh4[4], bl4[4];
            ldsm4(bh4, sb + R2_BHI + boff);
            ldsm4(bl4, sb + R2_BLO + boff);

            mma_bf16(d[0][0], ah0, bh4[0], bh4[1]);
            mma_bf16(d[0][1], ah0, bh4[2], bh4[3]);
            mma_bf16(d[0][0], ah0, bl4[0], bl4[1]);
            mma_bf16(d[0][1], ah0, bl4[2], bl4[3]);
            mma_bf16(d[0][0], al0, bh4[0], bh4[1]);
            mma_bf16(d[0][1], al0, bh4[2], bh4[3]);

            mma_bf16(d[1][0], ah1, bh4[0], bh4[1]);
            mma_bf16(d[1][1], ah1, bh4[2], bh4[3]);
            mma_bf16(d[1][0], ah1, bl4[0], bl4[1]);
            mma_bf16(d[1][1], ah1, bl4[2], bl4[3]);
            mma_bf16(d[1][0], al1, bh4[0], bh4[1]);
            mma_bf16(d[1][1], al1, bh4[2], bh4[3]);
        }

#pragma unroll
        for (int mt = 0; mt < 2; mt++) {
            int x = 32*xt + 16*mt + (lane >> 2);
            size_t vbase = ((size_t)b*VOL_FULL + ((size_t)z*128 + y0 + yr)*128 + x)*16;
#pragma unroll
            for (int nt = 0; nt < 2; nt++) {
                int c = 8*nt + 2*(lane & 3);
                *(float2*)(g_buf2 + vbase + c)       = make_float2(d[mt][nt][0], d[mt][nt][1]);
                *(float2*)(g_buf2 + vbase + 128 + c) = make_float2(d[mt][nt][2], d[mt][nt][3]);
                sacc[2*nt]   += d[mt][nt][0] + d[mt][nt][2];
                sacc[2*nt+1] += d[mt][nt][1] + d[mt][nt][3];
                qacc[2*nt]   += d[mt][nt][0]*d[mt][nt][0] + d[mt][nt][2]*d[mt][nt][2];
                qacc[2*nt+1] += d[mt][nt][1]*d[mt][nt][1] + d[mt][nt][3]*d[mt][nt][3];
            }
        }
    }

    __syncthreads();
    float* smS = (float*)smem;
    if (tid < 32) smS[tid] = 0.f;
    __syncthreads();
#pragma unroll
    for (int k = 0; k < 4; k++) {
        int c = 8*(k >> 1) + 2*(lane & 3) + (k & 1);
        atomicAdd(&smS[c], sacc[k]);
        atomicAdd(&smS[16 + c], qacc[k]);
    }
    __syncthreads();
    if (tid < 16) {
        int slot = (yq*8 + zs) & 63;
        atomicAdd(&g_redp[1][slot][tid],      (double)smS[tid]);
        atomicAdd(&g_redp[1][slot][32 + tid], (double)smS[16 + tid]);
    }
}

// ---------------------------------------------------------------------------
// conv3 ring (R11): stride-2 16->32 HMMA bf16x3.
#define C3_SLOT 20800
#define C3_ALO  83200
#define C3_BHI  166400
#define C3_BLO  194048
#define C3_SB   221696
#define C3_SMEM 221952

__global__ void __launch_bounds__(256, 1) k_conv3_ring()
{
    extern __shared__ __align__(16) char smem[];
    const uint32_t sb = smem_u32(smem);
    float* smSB = (float*)(smem + C3_SB);
    const int yq = blockIdx.x, zs = blockIdx.y, b = blockIdx.z;
    const int y0 = 2*yq, z0 = 16*zs;
    const int tid = threadIdx.x, wid = tid >> 5, lane = tid & 31;

    if (tid < 64) smSB[tid] = g_sbt[1][tid];

    for (int i = tid; i < 1728; i += 256) {
        int row = i >> 1, hf = i & 1;
        uint4 vh = *(const uint4*)(g_w3h + row*16 + hf*8);
        uint4 vl = *(const uint4*)(g_w3l + row*16 + hf*8);
        uint32_t off = (uint32_t)row*32 + (((uint32_t)hf ^ ((uint32_t)(row>>2)&1)) << 4);
        *(uint4*)(smem + C3_BHI + off) = vh;
        *(uint4*)(smem + C3_BLO + off) = vl;
    }
    __syncthreads();

    auto fillplane = [&](int p) {
        int slot = (p & 3);
        char* ah = smem + slot*C3_SLOT;
        char* al = smem + C3_ALO + slot*C3_SLOT;
        for (int i = tid; i < 650; i += 256) {
            int dyr = i / 130, xs = i - dyr*130;
            int gx = xs - 1, gy = 2*y0 - 1 + dyr;
            __align__(16) __nv_bfloat16 h[16], lo[16];
            if ((unsigned)p < 128u && (unsigned)gy < 128u && (unsigned)gx < 128u) {
                const float4* src = (const float4*)(g_buf2
                    + ((size_t)b*VOL_FULL + ((size_t)p*128 + gy)*128 + gx)*16);
                float4 q0 = src[0], q1 = src[1], q2 = src[2], q3 = src[3];
                float f[16] = {q0.x,q0.y,q0.z,q0.w, q1.x,q1.y,q1.z,q1.w,
                               q2.x,q2.y,q2.z,q2.w, q3.x,q3.y,q3.z,q3.w};
#pragma unroll
                for (int c = 0; c < 16; c++) {
                    float vv = fmaxf(fmaf(f[c], smSB[c], smSB[32 + c]), 0.f);
                    h[c] = __float2bfloat16(vv);
                    lo[c] = __float2bfloat16(vv - __bfloat162float(h[c]));
                }
            } else {
#pragma unroll
                for (int c = 0; c < 16; c++) { h[c] = __float2bfloat16(0.f); lo[c] = h[c]; }
            }
            uint32_t pb = (uint32_t)((i >> 2) & 1);
            uint32_t o0 = (uint32_t)i*32 + (pb << 4);
            uint32_t o1 = (uint32_t)i*32 + ((1u ^ pb) << 4);
            *(uint4*)(ah + o0) = *(uint4*)h;
            *(uint4*)(ah + o1) = *(uint4*)(h + 8);
            *(uint4*)(al + o0) = *(uint4*)lo;
            *(uint4*)(al + o1) = *(uint4*)(lo + 8);
        }
    };

    fillplane(2*z0 - 1);

    const int yrow = wid >> 2, xt = wid & 3;
    const int mrow = lane & 15;
    const uint32_t ahalf = (uint32_t)(lane >> 4);
    const int browl = ((lane >> 4) << 3) + (lane & 7);
    const uint32_t bhalf = (uint32_t)((lane >> 3) & 1);

    float sacc[8], qacc[8];
#pragma unroll
    for (int k = 0; k < 8; k++) { sacc[k] = 0.f; qacc[k] = 0.f; }

    for (int z = z0; z < z0 + 16; z++) {
        __syncthreads();
        fillplane(2*z);
        fillplane(2*z + 1);
        __syncthreads();

        uint32_t sb_a[3];
#pragma unroll
        for (int dz = 0; dz < 3; dz++)
            sb_a[dz] = (uint32_t)(((2*z - 1 + dz) & 3) * C3_SLOT);

        float d[4][4];
#pragma unroll
        for (int nt = 0; nt < 4; nt++)
#pragma unroll
            for (int i = 0; i < 4; i++) d[nt][i] = 0.f;

#pragma unroll
        for (int tap = 0; tap < 27; tap++) {
            const int zy = tap / 3, dx = tap % 3;
            const int dz = zy / 3, dy = zy % 3;
            int r = (2*yrow + dy)*130 + 2*(16*xt + mrow) + dx;
            uint32_t aoff = sb_a[dz] + (uint32_t)r*32
                          + ((ahalf ^ ((uint32_t)(r >> 2) & 1)) << 4);
            uint32_t ah4[4], al4[4];
            ldsm4(ah4, sb + aoff);
            ldsm4(al4, sb + C3_ALO + aoff);

#pragma unroll
            for (int gq = 0; gq < 2; gq++) {
                int br = tap*32 + gq*16 + browl;
                uint32_t boff = (uint32_t)br*32
                              + ((bhalf ^ ((uint32_t)(br >> 2) & 1)) << 4);
                uint32_t bh4[4], bl4[4];
                ldsm4(bh4, sb + C3_BHI + boff);
                ldsm4(bl4, sb + C3_BLO + boff);

                mma_bf16(d[2*gq],   ah4, bh4[0], bh4[1]);
                mma_bf16(d[2*gq+1], ah4, bh4[2], bh4[3]);
                mma_bf16(d[2*gq],   ah4, bl4[0], bl4[1]);
                mma_bf16(d[2*gq+1], ah4, bl4[2], bl4[3]);
                mma_bf16(d[2*gq],   al4, bh4[0], bh4[1]);
                mma_bf16(d[2*gq+1], al4, bh4[2], bh4[3]);
            }
        }

        const int y = y0 + yrow;
        const int xA = 16*xt + (lane >> 2);
#pragma unroll
        for (int nt = 0; nt < 4; nt++) {
            int c = 8*nt + 2*(lane & 3);
            size_t base0 = (size_t)(b*32 + c)*VOL_HALF + (size_t)z*4096 + y*64 + xA;
            g_buf3[base0]                = d[nt][0];
            g_buf3[base0 + VOL_HALF]     = d[nt][1];
            g_buf3[base0 + 8]            = d[nt][2];
            g_buf3[base0 + VOL_HALF + 8] = d[nt][3];
            sacc[2*nt]   += d[nt][0] + d[nt][2];
            sacc[2*nt+1] += d[nt][1] + d[nt][3];
            qacc[2*nt]   += d[nt][0]*d[nt][0] + d[nt][2]*d[nt][2];
            qacc[2*nt+1] += d[nt][1]*d[nt][1] + d[nt][3]*d[nt][3];
        }
    }

    __syncthreads();
    float* smS = (float*)smem;
    if (tid < 64) smS[tid] = 0.f;
    __syncthreads();
#pragma unroll
    for (int k = 0; k < 8; k++) {
        int c = 8*(k >> 1) + 2*(lane & 3) + (k & 1);
        atomicAdd(&smS[c], sacc[k]);
        atomicAdd(&smS[32 + c], qacc[k]);
    }
    __syncthreads();
    if (tid < 32) {
        int slot = (yq*4 + zs) & 63;
        atomicAdd(&g_redp[2][slot][tid],      (double)smS[tid]);
        atomicAdd(&g_redp[2][slot][32 + tid], (double)smS[32 + tid]);
    }
}

// ---------------------------------------------------------------------------
__global__ void __launch_bounds__(256) k_finalize(int stage, int C, float invN,
                                                  const float* __restrict__ g,
                                                  const float* __restrict__ b)
{
    __shared__ double sS[8][32], sQ[8][32];
    const int tid = threadIdx.x;
    const int c = tid & 31, part = tid >> 5;
    double s = 0.0, q = 0.0;
    for (int i = part; i < 64; i += 8) {
        s += g_redp[stage][i][c];
        q += g_redp[stage][i][32 + c];
    }
    sS[part][c] = s; sQ[part][c] = q;
    __syncthreads();
    if (tid < 32 && tid < C) {
        double S = 0.0, Q = 0.0;
#pragma unroll
        for (int p = 0; p < 8; p++) { S += sS[p][tid]; Q += sQ[p][tid]; }
        double mean = S * (double)invN;
        double var  = Q * (double)invN - mean*mean;
        float sc = g[tid] * rsqrtf((float)var + 1e-5f);
        g_sbt[stage][tid]      = sc;
        g_sbt[stage][32 + tid] = b[tid] - (float)mean * sc;
    }
}

// ---------------------------------------------------------------------------
// decompW + (folded) zeroing of g_gemm / g_redp.
__global__ void __launch_bounds__(256) k_decompW(const float* __restrict__ tok_w,
                                                 const float* __restrict__ aux_w)
{
    size_t gid = (size_t)blockIdx.x*256 + threadIdx.x;
    if (gid < 2*N_PATCH*N_T) g_gemm[gid] = 0.f;
    if (gid < 3*64*64) ((double*)g_redp)[gid] = 0.0;
    size_t e = gid*8;
    if (e >= (size_t)N_T*PDIM) return;
    int t = (int)(e >> 17);
    int k = (int)(e & (PDIM-1));
    const float* src = (t < 128) ? tok_w + ((size_t)t << 17) + k
                                 : aux_w + ((size_t)(t-128) << 17) + k;
    float4 a = ((const float4*)src)[0];
    float4 c = ((const float4*)src)[1];
    float v[8] = {a.x,a.y,a.z,a.w, c.x,c.y,c.z,c.w};
    __align__(16) __nv_bfloat16 h[8];
    __align__(16) __nv_bfloat16 l[8];
#pragma unroll
    for (int j = 0; j < 8; j++) {
        h[j] = __float2bfloat16(v[j]);
        l[j] = __float2bfloat16(v[j] - __bfloat162float(h[j]));
    }
    *(uint4*)(g_whi + e) = *(uint4*)h;
    *(uint4*)(g_wlo + e) = *(uint4*)l;
}

__global__ void __launch_bounds__(256) k_decompA()
{
    size_t gid = (size_t)blockIdx.x*256 + threadIdx.x;
    size_t e = gid*8;
    if (e >= (size_t)2*32*VOL_HALF) return;
    int ci = (int)((e >> 18) & 31);
    float s_ = g_sbt[2][ci], b_ = g_sbt[2][32 + ci];
    float4 a = *(const float4*)(g_buf3 + e);
    float4 c = *(const float4*)(g_buf3 + e + 4);
    float v[8] = {a.x,a.y,a.z,a.w, c.x,c.y,c.z,c.w};
    __align__(16) __nv_bfloat16 h[8];
    __align__(16) __nv_bfloat16 l[8];
#pragma unroll
    for (int j = 0; j < 8; j++) {
        float x = fmaxf(fmaf(v[j], s_, b_), 0.f);
        h[j] = __float2bfloat16(x);
        l[j] = __float2bfloat16(x - __bfloat162float(h[j]));
    }
    *(uint4*)(g_ahi + e) = *(uint4*)h;
    *(uint4*)(g_alo + e) = *(uint4*)l;
}

// ---------------------------------------------------------------------------
// HMMA bf16x3 patch GEMM, K-split x2, warp tile m32 x n80.
#define A_HI 0
#define A_LO 18432
#define B_HI 36864
#define B_LO 59904
#define GEMM_SMEM 82944

__global__ void __launch_bounds__(256, 2) k_gemm_tc()
{
    extern __shared__ __align__(16) char smem[];
    const uint32_t sb = smem_u32(smem);
    const int tile = blockIdx.x;
    const int ci = blockIdx.y >> 1, kh = blockIdx.y & 1;
    const int tid = threadIdx.x, w = tid >> 5, lane = tid & 31;
    const int mg = w & 3, ng = w >> 2;

    int m = tile*128 + tid;
    bool valid = (tid < 128) && (m < 686);
    int b = 0, pz = 0, py = 0, px = 0;
    if (valid) {
        b = (m >= 343) ? 1 : 0;
        int n = m - 343*b;
        pz = n / 49; int r2 = n - 49*pz;
        py = r2 / 7; px = r2 - 7*py;
    }
    const size_t chan = (size_t)(b*32 + ci)*64;

    uint32_t aHiB[2], aLoB[2];
#pragma unroll
    for (int mt = 0; mt < 2; mt++) {
        uint32_t off = (uint32_t)((32*mg + 16*mt + (lane & 15))*144 + ((lane >> 4)*8)*2);
        aHiB[mt] = sb + A_HI + off;
        aLoB[mt] = sb + A_LO + off;
    }
    const uint32_t bOff = (uint32_t)((((lane >> 4) << 3) + (lane & 7))*144
                                     + (((lane >> 3) & 1)*8)*2);
    const uint32_t bHiB = sb + B_HI + bOff;
    const uint32_t bLoB = sb + B_LO + bOff;

    float d[2][10][4];
#pragma unroll
    for (int mt = 0; mt < 2; mt++)
#pragma unroll
        for (int nt = 0; nt < 10; nt++)
#pragma unroll
            for (int i = 0; i < 4; i++) d[mt][nt][i] = 0.f;

    const size_t kcol = (size_t)ci*4096;

    for (int cc = 0; cc < 32; cc++) {
        const int chunk = kh*32 + cc;
        __syncthreads();

        if (tid < 128) {
            const int dz = chunk >> 2, dy0 = (chunk & 3) << 2;
#pragma unroll
            for (int j = 0; j < 4; j++) {
                uint4 h0 = make_uint4(0,0,0,0), h1 = h0, l0 = h0, l1 = h0;
                if (valid) {
                    size_t idx = (chan + 8*pz + dz)*4096
                               + (size_t)(8*py + dy0 + j)*64 + 8*px;
                    h0 = *(const uint4*)(g_ahi + idx);
                    h1 = *(const uint4*)(g_ahi + idx + 8);
                    l0 = *(const uint4*)(g_alo + idx);
                    l1 = *(const uint4*)(g_alo + idx + 8);
                }
                int dst = tid*144 + j*32;
                *(uint4*)(smem + A_HI + dst)      = h0;
                *(uint4*)(smem + A_HI + dst + 16) = h1;
                *(uint4*)(smem + A_LO + dst)      = l0;
                *(uint4*)(smem + A_LO + dst + 16) = l1;
            }
        }
        {
            const size_t kb = kcol + (size_t)chunk*64;
#pragma unroll
            for (int i = tid; i < 1280; i += 256) {
                int n = i >> 3, seg = i & 7;
                size_t so = (size_t)n*PDIM + kb + seg*8;
                int dst = n*144 + seg*16;
                *(uint4*)(smem + B_HI + dst) = *(const uint4*)(g_whi + so);
                *(uint4*)(smem + B_LO + dst) = *(const uint4*)(g_wlo + so);
            }
        }
        __syncthreads();

#pragma unroll
        for (int ks = 0; ks < 4; ks++) {
            uint32_t ah[2][4], al[2][4];
#pragma unroll
            for (int mt = 0; mt < 2; mt++) {
                ldsm4(ah[mt], aHiB[mt] + ks*32);
                ldsm4(al[mt], aLoB[mt] + ks*32);
            }
#pragma unroll
            for (int jg = 0; jg < 5; jg++) {
                const int j = 5*ng + jg;
                uint32_t bh[4], bl[4];
                ldsm4(bh, bHiB + j*2304 + ks*32);
                ldsm4(bl, bLoB + j*2304 + ks*32);
#pragma unroll
                for (int mt = 0; mt < 2; mt++) {
                    mma_bf16(d[mt][2*jg],   ah[mt], bh[0], bh[1]);
                    mma_bf16(d[mt][2*jg+1], ah[mt], bh[2], bh[3]);
                    mma_bf16(d[mt][2*jg],   ah[mt], bl[0], bl[1]);
                    mma_bf16(d[mt][2*jg+1], ah[mt], bl[2], bl[3]);
                    mma_bf16(d[mt][2*jg],   al[mt], bh[0], bh[1]);
                    mma_bf16(d[mt][2*jg+1], al[mt], bh[2], bh[3]);
                }
            }
        }
    }

    const int qc = 2*(lane & 3);
#pragma unroll
    for (int mt = 0; mt < 2; mt++) {
        const int mr = tile*128 + 32*mg + 16*mt + (lane >> 2);
#pragma unroll
        for (int nt = 0; nt < 10; nt++) {
            int col = 8*(10*ng + nt) + qc;
            if (mr < 686) {
                atomicAdd(&g_gemm[mr*N_T + col],     d[mt][nt][0]);
                atomicAdd(&g_gemm[mr*N_T + col + 1], d[mt][nt][1]);
            }
            if (mr + 8 < 686) {
                atomicAdd(&g_gemm[(mr+8)*N_T + col],     d[mt][nt][2]);
                atomicAdd(&g_gemm[(mr+8)*N_T + col + 1], d[mt][nt][3]);
            }
        }
    }
}

// ---------------------------------------------------------------------------
__global__ void k_final(const float* __restrict__ tok_b,
                        const float* __restrict__ aux_b,
                        const float* __restrict__ ln_g,
                        const float* __restrict__ ln_b,
                        float* __restrict__ out)
{
    const int bn = blockIdx.x;
    const int n = bn % N_PATCH;
    const int t = threadIdx.x;

    float v = g_gemm[bn*N_T + t] + tok_b[t];
    float s = v, q = v*v;
#pragma unroll
    for (int o = 16; o; o >>= 1) {
        s += __shfl_down_sync(0xffffffffu, s, o);
        q += __shfl_down_sync(0xffffffffu, q, o);
    }
    __shared__ float ss[4], qq[4];
    int wp = t >> 5, ln = t & 31;
    if (ln == 0) { ss[wp] = s; qq[wp] = q; }
    __syncthreads();
    float S1 = ss[0] + ss[1] + ss[2] + ss[3];
    float S2 = qq[0] + qq[1] + qq[2] + qq[3];
    float mean = S1 * (1.f/128.f);
    float var  = S2 * (1.f/128.f) - mean*mean;
    float r = rsqrtf(var + 1e-5f);

    out[bn*128 + t] = (v - mean) * r * ln_g[t] + ln_b[t];

    if (t < 32)
        out[87808 + bn*32 + t] = g_gemm[bn*N_T + 128 + t] + aux_b[t];

    if (t < 3) {
        int pz = n / 49, py = (n / 7) % 7, px = n % 7;
        float c;
        if      (t == 0) c = ((float)pz * 8.f + 7.5f) * (1.f/63.f);
        else if (t == 1) c = ((float)py * 8.f + 7.5f) * (1.f/63.f);
        else             c = ((float)px * 8.f + 7.5f) * (1.f/63.f);
        out[109760 + bn*3 + t] = c;
    }
}

// ---------------------------------------------------------------------------
extern "C" void kernel_launch(void* const* d_in, const int* in_sizes, int n_in,
                              void* d_out, int out_size) {
    const float* x     = (const float*)d_in[0];
    const float* c1w   = (const float*)d_in[1];
    const float* bn1g  = (const float*)d_in[2];
    const float* bn1b  = (const float*)d_in[3];
    const float* c2w   = (const float*)d_in[4];
    const float* bn2g  = (const float*)d_in[5];
    const float* bn2b  = (const float*)d_in[6];
    const float* c3w   = (const float*)d_in[7];
    const float* bn3g  = (const float*)d_in[8];
    const float* bn3b  = (const float*)d_in[9];
    const float* tokw  = (const float*)d_in[10];
    const float* tokb  = (const float*)d_in[11];
    const float* auxw  = (const float*)d_in[12];
    const float* auxb  = (const float*)d_in[13];
    const float* lng   = (const float*)d_in[14];
    const float* lnb   = (const float*)d_in[15];
    float* out = (float*)d_out;

    cudaFuncSetAttribute(k_gemm_tc, cudaFuncAttributeMaxDynamicSharedMemorySize,
                         GEMM_SMEM);
    cudaFuncSetAttribute(k_conv2_ring2, cudaFuncAttributeMaxDynamicSharedMemorySize,
                         R2_SMEM);
    cudaFuncSetAttribute(k_conv3_ring, cudaFuncAttributeMaxDynamicSharedMemorySize,
                         C3_SMEM);

    // decompW (+ folded zeroing of g_gemm / g_redp)
    k_decompW<<<(int)(((size_t)N_T*PDIM/8 + 255)/256), 256>>>(tokw, auxw);
    k_decompW23<<<1, 256>>>(c2w, c3w);

    // conv1 -> g_buf1 NHWC fp32 + stats 0
    k_conv1<<<dim3(64,128,2), 128>>>(x, c1w);
    k_finalize<<<1, 256>>>(0, 16, 1.f/(2.f*VOL_FULL), bn1g, bn1b);

    // conv2 (512-thr m32 HMMA ring) -> g_buf2 NHWC fp32 + stats 1
    k_conv2_ring2<<<dim3(32,8,2), 512, R2_SMEM>>>();
    k_finalize<<<1, 256>>>(1, 16, 1.f/(2.f*VOL_FULL), bn2g, bn2b);

    // conv3 (HMMA stride-2 ring) -> g_buf3 NCHW fp32 + stats 2
    k_conv3_ring<<<dim3(32,4,2), 256, C3_SMEM>>>();
    k_finalize<<<1, 256>>>(2, 32, 1.f/(2.f*VOL_HALF), bn3g, bn3b);

    // decompA
    k_decompA<<<(int)(((size_t)2*32*VOL_HALF/8 + 255)/256), 256>>>();

    // gemm (m32 x n80 warp tile, K-split x2)
    k_gemm_tc<<<dim3(6, 64), 256, GEMM_SMEM>>>();

    k_final<<<686, 128>>>(tokb, auxb, lng, lnb, out);
}